// round 14
// baseline (speedup 1.0000x reference)
#include <cuda_runtime.h>
#include <cuda_fp16.h>
#include <math.h>

#define NODES 16384
#define EDGES 262144
#define TSZ   14720
#define OUTC  304

// per-node t layout offsets (half elements), all [l][ang][c], c fastest
#define O000  0
#define O110  512
#define O220  2048
#define O011  6656
#define O101  7424
#define O121  7680
#define O211  9984
#define O111  10752
#define O022  11520
#define O112  12672
#define O202  13056
#define O222  13184
#define O212  14336

// transposed-P offsets in g_Pt (floats), layout [l][b][c] per family
#define T000  0
#define T110  32768
#define T220  49152
#define T011  57344
#define T101  65536
#define T121  81920
#define T211  86016
#define T111  94208
#define T022  102400
#define T112  104448
#define T202  108544
#define T222  116736
#define T212  118784
#define TPTOT 122880

#define NT 16                        // nodes per stage1 block
#define SX_SZ   (304 * NT)           // floats
#define STG_STR 260                  // floats per node row in staging
#define STG_HALF (NT * STG_STR)
#define S1_SMEM ((SX_SZ + 2 * STG_HALF) * 4)

#define HIST_BLOCKS  (EDGES / 256)   // 1024
#define TP_BLOCKS    (TPTOT / 256 + 1)
#define S1_BLOCKS    (NODES / NT)    // 1024

typedef unsigned long long ull;

__device__ __half g_t[(size_t)NODES * TSZ];           // 482 MB scratch (fp16)
__device__ float  g_m[(size_t)EDGES * OUTC];          // 319 MB per-edge messages
__device__ float  g_Pt[TPTOT];                        // transposed P, c-fastest
__device__ int g_cntS[NODES], g_curS[NODES], g_startS[NODES + 1], g_sortS[EDGES];
__device__ int g_cntD[NODES], g_curD[NODES], g_startD[NODES + 1], g_sortD[EDGES];

// ---- packed f32x2 helpers ----
__device__ __forceinline__ ull dup2(float x) {
    ull r; asm("mov.b64 %0, {%1, %1};" : "=l"(r) : "f"(x)); return r;
}
__device__ __forceinline__ void fma2(ull& a, ull b, ull c) {
    asm("fma.rn.f32x2 %0, %1, %2, %0;" : "+l"(a) : "l"(b), "l"(c));
}
__device__ __forceinline__ float2 unpk2(ull a) {
    float2 f; asm("mov.b64 {%0, %1}, %2;" : "=f"(f.x), "=f"(f.y) : "l"(a)); return f;
}

// ---------------- P transpose helper: P[c][l][b] -> Pt[l][b][c] ----------------
__device__ __forceinline__ void tp1(const float* __restrict__ P, float* __restrict__ Pt,
                                    int i, int C, int B) {
    const int b = i % B;
    const int l = (i / B) % 8;
    const int c = i / (8 * B);
    Pt[(l * B + b) * C + c] = P[i];
}

// ---------------- launch 1: histS + histD + transpose fused ----------------
__global__ void prep_kernel(
    const int* __restrict__ src, const int* __restrict__ dst,
    const float* __restrict__ P000, const float* __restrict__ P110, const float* __restrict__ P220,
    const float* __restrict__ P011, const float* __restrict__ P101, const float* __restrict__ P121,
    const float* __restrict__ P211, const float* __restrict__ P111, const float* __restrict__ P022,
    const float* __restrict__ P112, const float* __restrict__ P202, const float* __restrict__ P222,
    const float* __restrict__ P212)
{
    if (blockIdx.x < HIST_BLOCKS) {
        int i = blockIdx.x * 256 + threadIdx.x;
        atomicAdd(&g_cntS[src[i]], 1);
    } else if (blockIdx.x < 2 * HIST_BLOCKS) {
        int i = (blockIdx.x - HIST_BLOCKS) * 256 + threadIdx.x;
        atomicAdd(&g_cntD[dst[i]], 1);
    } else {
        int i = (blockIdx.x - 2 * HIST_BLOCKS) * 256 + threadIdx.x;
        if      (i < T110)  tp1(P000, g_Pt + T000, i - T000, 64, 64);
        else if (i < T220)  tp1(P110, g_Pt + T110, i - T110, 64, 32);
        else if (i < T011)  tp1(P220, g_Pt + T220, i - T220, 64, 16);
        else if (i < T101)  tp1(P011, g_Pt + T011, i - T011, 32, 32);
        else if (i < T121)  tp1(P101, g_Pt + T101, i - T101, 32, 64);
        else if (i < T211)  tp1(P121, g_Pt + T121, i - T121, 32, 16);
        else if (i < T111)  tp1(P211, g_Pt + T211, i - T211, 32, 32);
        else if (i < T022)  tp1(P111, g_Pt + T111, i - T111, 32, 32);
        else if (i < T112)  tp1(P022, g_Pt + T022, i - T022, 16, 16);
        else if (i < T202)  tp1(P112, g_Pt + T112, i - T112, 16, 32);
        else if (i < T222)  tp1(P202, g_Pt + T202, i - T202, 16, 64);
        else if (i < T212)  tp1(P222, g_Pt + T222, i - T222, 16, 16);
        else if (i < TPTOT) tp1(P212, g_Pt + T212, i - T212, 16, 32);
    }
}

// ---------------- launch 2: both scans, one kernel ----------------
__device__ __forceinline__ void scan_body(const int* __restrict__ cnt, int* __restrict__ start) {
    __shared__ int ssum[1024];
    int t = threadIdx.x;
    int loc[16];
    int s = 0;
    int base = t * 16;
    #pragma unroll
    for (int i = 0; i < 16; i++) { loc[i] = s; s += cnt[base + i]; }
    ssum[t] = s;
    __syncthreads();
    for (int off = 1; off < 1024; off <<= 1) {
        int v = (t >= off) ? ssum[t - off] : 0;
        __syncthreads();
        if (t >= off) ssum[t] += v;
        __syncthreads();
    }
    int excl = (t == 0) ? 0 : ssum[t - 1];
    #pragma unroll
    for (int i = 0; i < 16; i++) start[base + i] = excl + loc[i];
    if (t == 0) start[NODES] = EDGES;
}

__global__ void scan2_kernel() {
    if (blockIdx.x == 0) scan_body(g_cntS, g_startS);
    else                 scan_body(g_cntD, g_startD);
}

// ---------------- stage 1 (R7): f32x2, l-paired, staged flush ----------------

__device__ __forceinline__ void flush_chunk16(const float* __restrict__ stg,
                                              __half* __restrict__ tg,
                                              int off, int cols) {
    const int warp = threadIdx.x >> 5, lane = threadIdx.x & 31;
    if (lane * 8 < cols) {
        #pragma unroll
        for (int n2 = 0; n2 < 2; n2++) {
            const int n = warp * 2 + n2;
            const float* s = stg + n * STG_STR + lane * 8;
            float4 f0 = *reinterpret_cast<const float4*>(s);
            float4 f1 = *reinterpret_cast<const float4*>(s + 4);
            __half2 h0 = __floats2half2_rn(f0.x, f0.y);
            __half2 h1 = __floats2half2_rn(f0.z, f0.w);
            __half2 h2 = __floats2half2_rn(f1.x, f1.y);
            __half2 h3 = __floats2half2_rn(f1.z, f1.w);
            uint4 v;
            v.x = *reinterpret_cast<unsigned*>(&h0);
            v.y = *reinterpret_cast<unsigned*>(&h1);
            v.z = *reinterpret_cast<unsigned*>(&h2);
            v.w = *reinterpret_cast<unsigned*>(&h3);
            *reinterpret_cast<uint4*>(tg + (size_t)n * TSZ + off + lane * 8) = v;
        }
    }
}

template<int C, int B, int ANG, int ANGX>
__device__ __forceinline__ void fam3(const float* __restrict__ Pt,
                                     const float* __restrict__ sx,
                                     int xoff, float* __restrict__ stgA,
                                     float* __restrict__ stgB,
                                     __half* __restrict__ tg, int toff) {
    const int tid = threadIdx.x;
    const int NEH = 4 * ANG * C;
    for (int cb = 0; cb < NEH; cb += 256) {
        const int e = cb + tid;
        if (e < NEH) {
            const int c  = e % C;
            const int la = e / C;
            const int a  = la % ANG;
            const int l  = la / ANG;
            const ull* xb = reinterpret_cast<const ull*>(sx) + (xoff + a) * (NT / 2);
            ull acc0[8], acc1[8];
            #pragma unroll
            for (int np = 0; np < 8; np++) { acc0[np] = 0ull; acc1[np] = 0ull; }
            const float* PlA = Pt + (l * B) * C + c;
            const float* PlB = Pt + ((l + 4) * B) * C + c;
            #pragma unroll 1
            for (int bc = 0; bc < B; bc += 8) {
                ull pA[8], pB[8];
                #pragma unroll
                for (int j = 0; j < 8; j++) {
                    pA[j] = dup2(PlA[(bc + j) * C]);
                    pB[j] = dup2(PlB[(bc + j) * C]);
                }
                #pragma unroll
                for (int j = 0; j < 8; j++) {
                    #pragma unroll
                    for (int np = 0; np < 8; np++) {
                        ull xv = xb[(bc + j) * ANGX * 8 + np];
                        fma2(acc0[np], pA[j], xv);
                        fma2(acc1[np], pB[j], xv);
                    }
                }
            }
            #pragma unroll
            for (int np = 0; np < 8; np++) {
                float2 r0 = unpk2(acc0[np]);
                float2 r1 = unpk2(acc1[np]);
                stgA[(2 * np)     * STG_STR + tid] = r0.x;
                stgA[(2 * np + 1) * STG_STR + tid] = r0.y;
                stgB[(2 * np)     * STG_STR + tid] = r1.x;
                stgB[(2 * np + 1) * STG_STR + tid] = r1.y;
            }
        }
        __syncthreads();
        const int cols = min(256, NEH - cb);
        flush_chunk16(stgA, tg, toff + cb, cols);
        flush_chunk16(stgB, tg, toff + NEH + cb, cols);
        __syncthreads();
    }
}

__device__ __forceinline__ void stage1_body(
    const float* __restrict__ xa, const float* __restrict__ xv, const float* __restrict__ xd,
    int blk)
{
    extern __shared__ float smem[];
    float* sx   = smem;
    float* stgA = smem + SX_SZ;
    float* stgB = smem + SX_SZ + STG_HALF;
    const int node0 = blk * NT;
    const int tid = threadIdx.x;
    for (int i = tid; i < NT * 64;  i += 256) { int n = i / 64,  f = i % 64;        sx[f * 16 + n] = xa[node0 * 64  + i]; }
    for (int i = tid; i < NT * 96;  i += 256) { int n = i / 96,  f = 64 + i % 96;   sx[f * 16 + n] = xv[node0 * 96  + i]; }
    for (int i = tid; i < NT * 144; i += 256) { int n = i / 144, f = 160 + i % 144; sx[f * 16 + n] = xd[node0 * 144 + i]; }
    __syncthreads();
    __half* tg = g_t + (size_t)node0 * TSZ;
    fam3<64, 64, 1, 1>(g_Pt + T000, sx, 0,   stgA, stgB, tg, O000);
    fam3<32, 64, 1, 1>(g_Pt + T101, sx, 0,   stgA, stgB, tg, O101);
    fam3<16, 64, 1, 1>(g_Pt + T202, sx, 0,   stgA, stgB, tg, O202);
    fam3<64, 32, 3, 3>(g_Pt + T110, sx, 64,  stgA, stgB, tg, O110);
    fam3<64, 16, 9, 9>(g_Pt + T220, sx, 160, stgA, stgB, tg, O220);
    fam3<32, 32, 3, 3>(g_Pt + T011, sx, 64,  stgA, stgB, tg, O011);
    fam3<32, 16, 9, 9>(g_Pt + T121, sx, 160, stgA, stgB, tg, O121);
    fam3<32, 32, 3, 3>(g_Pt + T211, sx, 64,  stgA, stgB, tg, O211);
    fam3<32, 32, 3, 3>(g_Pt + T111, sx, 64,  stgA, stgB, tg, O111);
    fam3<16, 16, 9, 9>(g_Pt + T022, sx, 160, stgA, stgB, tg, O022);
    fam3<16, 32, 3, 3>(g_Pt + T112, sx, 64,  stgA, stgB, tg, O112);
    fam3<16, 16, 9, 9>(g_Pt + T222, sx, 160, stgA, stgB, tg, O222);
    fam3<16, 32, 3, 3>(g_Pt + T212, sx, 64,  stgA, stgB, tg, O212);
}

// ---------------- launch 3: scatterS + scatterD + stage1 fused ----------------
__global__ void __launch_bounds__(256, 2) combo_kernel(
    const int* __restrict__ src, const int* __restrict__ dst,
    const float* __restrict__ xa, const float* __restrict__ xv, const float* __restrict__ xd)
{
    if (blockIdx.x < HIST_BLOCKS) {
        int i = blockIdx.x * 256 + threadIdx.x;
        int sn = src[i];
        int p = g_startS[sn] + atomicAdd(&g_curS[sn], 1);
        g_sortS[p] = i;
    } else if (blockIdx.x < 2 * HIST_BLOCKS) {
        int i = (blockIdx.x - HIST_BLOCKS) * 256 + threadIdx.x;
        int dn = dst[i];
        int p = g_startD[dn] + atomicAdd(&g_curD[dn], 1);
        g_sortD[p] = i;
    } else {
        stage1_body(xa, xv, xd, blockIdx.x - 2 * HIST_BLOCKS);
    }
}

// ---------------- stage 2a: per-edge contraction, fp16 smem tile, fast geom ----------------

__device__ __forceinline__ void edge_geom(const float* __restrict__ rij, int e,
                                          float* rad, float* rh, float* rr) {
    const float rx = rij[3 * e + 0], ry = rij[3 * e + 1], rz = rij[3 * e + 2];
    const float xsq = (rx * rx + ry * ry + rz * rz) * 0.125f;
    const float env = fmaxf(0.f, 1.f - xsq);
    const float c1  = __cosf(3.14159265358979f * sqrtf(xsq));
    rad[0] = env; rad[1] = c1 * env;
    float cm2 = 1.f, cm1 = c1;
    #pragma unroll
    for (int l = 2; l < 8; l++) {
        float cn = 2.f * c1 * cm1 - cm2;
        rad[l] = cn * env;
        cm2 = cm1; cm1 = cn;
    }
    const float vx = rx * 0.875f, vy = ry * 0.875f, vz = rz * 0.875f;
    const float nr = sqrtf(vx * vx + vy * vy + vz * vz);
    // fast tanh(nr)/nr
    const float e2 = __expf(2.f * nr);
    const float t  = 1.f - __fdividef(2.f, e2 + 1.f);
    const float sc = __fdividef(t, fmaxf(nr, 1e-6f));
    rh[0] = vx * sc; rh[1] = vy * sc; rh[2] = vz * sc;
    #pragma unroll
    for (int i = 0; i < 3; i++)
        #pragma unroll
        for (int j = 0; j < 3; j++) rr[i * 3 + j] = rh[i] * rh[j];
}

__device__ __forceinline__ float ldh(const __half* __restrict__ st, int idx) {
    return __half2float(st[idx]);
}

__global__ void __launch_bounds__(256, 4) edge_kernel(
    const float* __restrict__ rij)
{
    extern __shared__ __half st[];
    const int n   = blockIdx.x;
    const int tid = threadIdx.x;
    // raw fp16 tile copy (no conversion)
    {
        const uint4* tg = reinterpret_cast<const uint4*>(g_t + (size_t)n * TSZ);
        uint4* st4 = reinterpret_cast<uint4*>(st);
        for (int i = tid; i < TSZ / 8; i += 256) st4[i] = tg[i];
    }
    __syncthreads();
    const int s0 = g_startS[n], s1 = g_startS[n + 1];
    const int warp = tid >> 5, lane = tid & 31;
    const int c16 = lane & 15;

    for (int k = s0 + 2 * warp; k < s1; k += 16) {
        const int eA = g_sortS[k];
        const bool vB = (k + 1 < s1);
        const int eB = g_sortS[vB ? k + 1 : k];
        float* mA = g_m + (size_t)eA * OUTC;
        float* mB = g_m + (size_t)eB * OUTC;
        float radA[8], rhA[3], rrA[9], radB[8], rhB[3], rrB[9];
        edge_geom(rij, eA, radA, rhA, rrA);
        edge_geom(rij, eB, radB, rhB, rrB);

        // ---------- m_a : channels 2*lane, 2*lane+1 via half2 loads ----------
        {
            float a0A = 0.f, a1A = 0.f, a0B = 0.f, a1B = 0.f;
            #pragma unroll
            for (int l = 0; l < 8; l++) {
                const float2 p0 = __half22float2(*reinterpret_cast<const __half2*>(st + O000 + l * 64 + 2 * lane));
                float sxA = p0.x, syA = p0.y, sxB = p0.x, syB = p0.y;
                #pragma unroll
                for (int i = 0; i < 3; i++) {
                    const float2 p = __half22float2(*reinterpret_cast<const __half2*>(st + O110 + (l * 3 + i) * 64 + 2 * lane));
                    sxA += rhA[i] * p.x; syA += rhA[i] * p.y;
                    sxB += rhB[i] * p.x; syB += rhB[i] * p.y;
                }
                #pragma unroll
                for (int a = 0; a < 9; a++) {
                    const float2 p = __half22float2(*reinterpret_cast<const __half2*>(st + O220 + (l * 9 + a) * 64 + 2 * lane));
                    sxA += rrA[a] * p.x; syA += rrA[a] * p.y;
                    sxB += rrB[a] * p.x; syB += rrB[a] * p.y;
                }
                a0A += radA[l] * sxA; a1A += radA[l] * syA;
                a0B += radB[l] * sxB; a1B += radB[l] * syB;
            }
            *reinterpret_cast<float2*>(mA + 2 * lane) = make_float2(a0A, a1A);
            if (vB) *reinterpret_cast<float2*>(mB + 2 * lane) = make_float2(a0B, a1B);
        }

        // ---------- m_v : channel c = lane ----------
        {
            float vA[3] = {0, 0, 0}, uA[3] = {0, 0, 0}, SA = 0.f;
            float vB3[3] = {0, 0, 0}, uB[3] = {0, 0, 0}, SB = 0.f;
            #pragma unroll
            for (int l = 0; l < 8; l++) {
                float t011[3], t211[3], t111[3], t121[9];
                const float t101 = ldh(st, O101 + l * 32 + lane);
                #pragma unroll
                for (int i = 0; i < 3; i++) {
                    t011[i] = ldh(st, O011 + (l * 3 + i) * 32 + lane);
                    t211[i] = ldh(st, O211 + (l * 3 + i) * 32 + lane);
                    t111[i] = ldh(st, O111 + (l * 3 + i) * 32 + lane);
                }
                #pragma unroll
                for (int a = 0; a < 9; a++) t121[a] = ldh(st, O121 + (l * 9 + a) * 32 + lane);

                float sSA = t101, sSB = t101;
                #pragma unroll
                for (int j = 0; j < 3; j++) { sSA += rhA[j] * t211[j]; sSB += rhB[j] * t211[j]; }
                SA += radA[l] * sSA; SB += radB[l] * sSB;
                #pragma unroll
                for (int i = 0; i < 3; i++) {
                    float svA = t011[i], svB = t011[i];
                    #pragma unroll
                    for (int j = 0; j < 3; j++) {
                        svA += rhA[j] * t121[i * 3 + j];
                        svB += rhB[j] * t121[i * 3 + j];
                    }
                    vA[i]  += radA[l] * svA;
                    vB3[i] += radB[l] * svB;
                    uA[i]  += radA[l] * t111[i];
                    uB[i]  += radB[l] * t111[i];
                }
            }
            vA[0]  += SA * rhA[0] + (rhA[1] * uA[2] - rhA[2] * uA[1]);
            vA[1]  += SA * rhA[1] + (rhA[2] * uA[0] - rhA[0] * uA[2]);
            vA[2]  += SA * rhA[2] + (rhA[0] * uA[1] - rhA[1] * uA[0]);
            vB3[0] += SB * rhB[0] + (rhB[1] * uB[2] - rhB[2] * uB[1]);
            vB3[1] += SB * rhB[1] + (rhB[2] * uB[0] - rhB[0] * uB[2]);
            vB3[2] += SB * rhB[2] + (rhB[0] * uB[1] - rhB[1] * uB[0]);
            #pragma unroll
            for (int i = 0; i < 3; i++) mA[64 + lane * 3 + i] = vA[i];
            if (vB) {
                #pragma unroll
                for (int i = 0; i < 3; i++) mB[64 + lane * 3 + i] = vB3[i];
            }
        }

        // ---------- m_d : c = lane&15, half-warps split the l-sum (rr folded into q) ----------
        {
            const int hh = lane >> 4;
            float radhA[4], radhB[4];
            #pragma unroll
            for (int i = 0; i < 4; i++) {
                radhA[i] = (hh == 0) ? radA[i] : radA[4 + i];
                radhB[i] = (hh == 0) ? radB[i] : radB[4 + i];
            }
            float outA[9] = {0,0,0,0,0,0,0,0,0};
            float outB[9] = {0,0,0,0,0,0,0,0,0};
            #pragma unroll
            for (int ll = 0; ll < 4; ll++) {
                const int l = hh * 4 + ll;
                float t022[9], t222[9], t112[3], t212[3];
                const float t202 = ldh(st, O202 + l * 16 + c16);
                #pragma unroll
                for (int a = 0; a < 9; a++) {
                    t022[a] = ldh(st, O022 + (l * 9 + a) * 16 + c16);
                    t222[a] = ldh(st, O222 + (l * 9 + a) * 16 + c16);
                }
                #pragma unroll
                for (int j = 0; j < 3; j++) {
                    t112[j] = ldh(st, O112 + (l * 3 + j) * 16 + c16);
                    t212[j] = ldh(st, O212 + (l * 3 + j) * 16 + c16);
                }
                float qA[3], qB[3];
                #pragma unroll
                for (int j = 0; j < 3; j++) {
                    qA[j] = t112[j] + rhA[0] * t222[j] + rhA[1] * t222[3 + j] + rhA[2] * t222[6 + j] + rhA[j] * t202;
                    qB[j] = t112[j] + rhB[0] * t222[j] + rhB[1] * t222[3 + j] + rhB[2] * t222[6 + j] + rhB[j] * t202;
                }
                qA[0] += rhA[1] * t212[2] - rhA[2] * t212[1];
                qA[1] += rhA[2] * t212[0] - rhA[0] * t212[2];
                qA[2] += rhA[0] * t212[1] - rhA[1] * t212[0];
                qB[0] += rhB[1] * t212[2] - rhB[2] * t212[1];
                qB[1] += rhB[2] * t212[0] - rhB[0] * t212[2];
                qB[2] += rhB[0] * t212[1] - rhB[1] * t212[0];
                #pragma unroll
                for (int ij = 0; ij < 9; ij++) {
                    const int i = ij / 3, j = ij % 3;
                    outA[ij] += radhA[ll] * (t022[ij] + rhA[i] * qA[j]);
                    outB[ij] += radhB[ll] * (t022[ij] + rhB[i] * qB[j]);
                }
            }
            #pragma unroll
            for (int ij = 0; ij < 9; ij++) {
                outA[ij] += __shfl_xor_sync(0xffffffffu, outA[ij], 16);
                outB[ij] += __shfl_xor_sync(0xffffffffu, outB[ij], 16);
            }
            #pragma unroll
            for (int ij = 0; ij < 9; ij++) {
                const bool mine = (hh == 0) ? (ij < 5) : (ij >= 5);
                if (mine) {
                    mA[160 + c16 * 9 + ij] = outA[ij];
                    if (vB) mB[160 + c16 * 9 + ij] = outB[ij];
                }
            }
        }
    }
}

// ---------------- launch 5: dst-grouped segment sum ----------------
__global__ void __launch_bounds__(256) gather_kernel(float* __restrict__ out) {
    const int warp = threadIdx.x >> 5, lane = threadIdx.x & 31;
    const int node = blockIdx.x * 8 + warp;
    float4 acc0 = make_float4(0, 0, 0, 0);
    float4 acc1 = make_float4(0, 0, 0, 0);
    float4 acc2 = make_float4(0, 0, 0, 0);
    const int q0 = lane, q1 = lane + 32, q2 = lane + 64;
    const int s0 = g_startD[node], s1 = g_startD[node + 1];
    for (int k = s0; k < s1; k++) {
        const int e = g_sortD[k];
        const float4* row = reinterpret_cast<const float4*>(g_m + (size_t)e * OUTC);
        float4 r0 = row[q0];
        float4 r1 = row[q1];
        acc0.x += r0.x; acc0.y += r0.y; acc0.z += r0.z; acc0.w += r0.w;
        acc1.x += r1.x; acc1.y += r1.y; acc1.z += r1.z; acc1.w += r1.w;
        if (lane < 12) {
            float4 r2 = row[q2];
            acc2.x += r2.x; acc2.y += r2.y; acc2.z += r2.z; acc2.w += r2.w;
        }
    }
    float4* orow = reinterpret_cast<float4*>(out + (size_t)node * OUTC);
    orow[q0] = acc0;
    orow[q1] = acc1;
    if (lane < 12) orow[q2] = acc2;

    const int gt = blockIdx.x * 256 + threadIdx.x;
    if (gt < NODES) { g_cntS[gt] = 0; g_curS[gt] = 0; g_cntD[gt] = 0; g_curD[gt] = 0; }
}

extern "C" void kernel_launch(void* const* d_in, const int* in_sizes, int n_in,
                              void* d_out, int out_size) {
    const float* x_a  = (const float*)d_in[0];
    const float* x_v  = (const float*)d_in[1];
    const float* x_d  = (const float*)d_in[2];
    const float* rij  = (const float*)d_in[3];
    const float* P000 = (const float*)d_in[4];
    const float* P110 = (const float*)d_in[5];
    const float* P220 = (const float*)d_in[6];
    const float* P011 = (const float*)d_in[7];
    const float* P101 = (const float*)d_in[8];
    const float* P121 = (const float*)d_in[9];
    const float* P211 = (const float*)d_in[10];
    const float* P111 = (const float*)d_in[11];
    const float* P022 = (const float*)d_in[12];
    const float* P112 = (const float*)d_in[13];
    const float* P202 = (const float*)d_in[14];
    const float* P222 = (const float*)d_in[15];
    const float* P212 = (const float*)d_in[16];
    const int*   src  = (const int*)d_in[17];
    const int*   dst  = (const int*)d_in[18];
    float* out = (float*)d_out;

    cudaFuncSetAttribute(combo_kernel, cudaFuncAttributeMaxDynamicSharedMemorySize, S1_SMEM);
    cudaFuncSetAttribute(edge_kernel,  cudaFuncAttributeMaxDynamicSharedMemorySize, TSZ * 2);

    // 1: histS + histD + P-transpose
    prep_kernel<<<2 * HIST_BLOCKS + TP_BLOCKS, 256>>>(src, dst,
                                                      P000, P110, P220, P011, P101,
                                                      P121, P211, P111, P022, P112,
                                                      P202, P222, P212);
    // 2: both scans
    scan2_kernel<<<2, 1024>>>();
    // 3: scatterS + scatterD + stage1
    combo_kernel<<<2 * HIST_BLOCKS + S1_BLOCKS, 256, S1_SMEM>>>(src, dst, x_a, x_v, x_d);
    // 4: edge  <-- ncu capture slot
    edge_kernel<<<NODES, 256, TSZ * 2>>>(rij);
    // 5: gather
    gather_kernel<<<NODES / 8, 256>>>(out);
}

// round 15
// speedup vs baseline: 2.1187x; 2.1187x over previous
#include <cuda_runtime.h>
#include <cuda_fp16.h>
#include <math.h>

#define NODES 16384
#define EDGES 262144
#define TSZ   14720
#define OUTC  304

// per-node t layout offsets (half elements), all [l][ang][c], c fastest
#define O000  0
#define O110  512
#define O220  2048
#define O011  6656
#define O101  7424
#define O121  7680
#define O211  9984
#define O111  10752
#define O022  11520
#define O112  12672
#define O202  13056
#define O222  13184
#define O212  14336

// transposed-P offsets in g_Pt (floats), layout [l][b][c] per family
#define T000  0
#define T110  32768
#define T220  49152
#define T011  57344
#define T101  65536
#define T121  81920
#define T211  86016
#define T111  94208
#define T022  102400
#define T112  104448
#define T202  108544
#define T222  116736
#define T212  118784
#define TPTOT 122880

#define NT 16                        // nodes per stage1 block
#define SX_SZ   (304 * NT)           // floats
#define STG_STR 260                  // floats per node row in staging
#define STG_HALF (NT * STG_STR)
#define S1_SMEM ((SX_SZ + 2 * STG_HALF) * 4)

#define HIST_BLOCKS  (EDGES / 256)   // 1024
#define TP_BLOCKS    (TPTOT / 256 + 1)
#define S1_BLOCKS    (NODES / NT)    // 1024

typedef unsigned long long ull;

__device__ __half g_t[(size_t)NODES * TSZ];           // 482 MB scratch (fp16)
__device__ float  g_m[(size_t)EDGES * OUTC];          // 319 MB per-edge messages
__device__ float  g_Pt[TPTOT];                        // transposed P, c-fastest
__device__ int g_cntS[NODES], g_curS[NODES], g_startS[NODES + 1], g_sortS[EDGES];
__device__ int g_cntD[NODES], g_curD[NODES], g_startD[NODES + 1], g_sortD[EDGES];

// ---- packed f32x2 helpers ----
__device__ __forceinline__ ull dup2(float x) {
    ull r; asm("mov.b64 %0, {%1, %1};" : "=l"(r) : "f"(x)); return r;
}
__device__ __forceinline__ void fma2(ull& a, ull b, ull c) {
    asm("fma.rn.f32x2 %0, %1, %2, %0;" : "+l"(a) : "l"(b), "l"(c));
}
__device__ __forceinline__ float2 unpk2(ull a) {
    float2 f; asm("mov.b64 {%0, %1}, %2;" : "=f"(f.x), "=f"(f.y) : "l"(a)); return f;
}

// ---------------- P transpose helper: P[c][l][b] -> Pt[l][b][c] ----------------
__device__ __forceinline__ void tp1(const float* __restrict__ P, float* __restrict__ Pt,
                                    int i, int C, int B) {
    const int b = i % B;
    const int l = (i / B) % 8;
    const int c = i / (8 * B);
    Pt[(l * B + b) * C + c] = P[i];
}

// ---------------- launch 1: histS + histD + transpose fused ----------------
__global__ void prep_kernel(
    const int* __restrict__ src, const int* __restrict__ dst,
    const float* __restrict__ P000, const float* __restrict__ P110, const float* __restrict__ P220,
    const float* __restrict__ P011, const float* __restrict__ P101, const float* __restrict__ P121,
    const float* __restrict__ P211, const float* __restrict__ P111, const float* __restrict__ P022,
    const float* __restrict__ P112, const float* __restrict__ P202, const float* __restrict__ P222,
    const float* __restrict__ P212)
{
    if (blockIdx.x < HIST_BLOCKS) {
        int i = blockIdx.x * 256 + threadIdx.x;
        atomicAdd(&g_cntS[src[i]], 1);
    } else if (blockIdx.x < 2 * HIST_BLOCKS) {
        int i = (blockIdx.x - HIST_BLOCKS) * 256 + threadIdx.x;
        atomicAdd(&g_cntD[dst[i]], 1);
    } else {
        int i = (blockIdx.x - 2 * HIST_BLOCKS) * 256 + threadIdx.x;
        if      (i < T110)  tp1(P000, g_Pt + T000, i - T000, 64, 64);
        else if (i < T220)  tp1(P110, g_Pt + T110, i - T110, 64, 32);
        else if (i < T011)  tp1(P220, g_Pt + T220, i - T220, 64, 16);
        else if (i < T101)  tp1(P011, g_Pt + T011, i - T011, 32, 32);
        else if (i < T121)  tp1(P101, g_Pt + T101, i - T101, 32, 64);
        else if (i < T211)  tp1(P121, g_Pt + T121, i - T121, 32, 16);
        else if (i < T111)  tp1(P211, g_Pt + T211, i - T211, 32, 32);
        else if (i < T022)  tp1(P111, g_Pt + T111, i - T111, 32, 32);
        else if (i < T112)  tp1(P022, g_Pt + T022, i - T022, 16, 16);
        else if (i < T202)  tp1(P112, g_Pt + T112, i - T112, 16, 32);
        else if (i < T222)  tp1(P202, g_Pt + T202, i - T202, 16, 64);
        else if (i < T212)  tp1(P222, g_Pt + T222, i - T222, 16, 16);
        else if (i < TPTOT) tp1(P212, g_Pt + T212, i - T212, 16, 32);
    }
}

// ---------------- launch 2: both scans, one kernel ----------------
__device__ __forceinline__ void scan_body(const int* __restrict__ cnt, int* __restrict__ start) {
    __shared__ int ssum[1024];
    int t = threadIdx.x;
    int loc[16];
    int s = 0;
    int base = t * 16;
    #pragma unroll
    for (int i = 0; i < 16; i++) { loc[i] = s; s += cnt[base + i]; }
    ssum[t] = s;
    __syncthreads();
    for (int off = 1; off < 1024; off <<= 1) {
        int v = (t >= off) ? ssum[t - off] : 0;
        __syncthreads();
        if (t >= off) ssum[t] += v;
        __syncthreads();
    }
    int excl = (t == 0) ? 0 : ssum[t - 1];
    #pragma unroll
    for (int i = 0; i < 16; i++) start[base + i] = excl + loc[i];
    if (t == 0) start[NODES] = EDGES;
}

__global__ void scan2_kernel() {
    if (blockIdx.x == 0) scan_body(g_cntS, g_startS);
    else                 scan_body(g_cntD, g_startD);
}

// ---------------- stage 1 (R7): f32x2, l-paired, staged flush ----------------

__device__ __forceinline__ void flush_chunk16(const float* __restrict__ stg,
                                              __half* __restrict__ tg,
                                              int off, int cols) {
    const int warp = threadIdx.x >> 5, lane = threadIdx.x & 31;
    if (lane * 8 < cols) {
        #pragma unroll
        for (int n2 = 0; n2 < 2; n2++) {
            const int n = warp * 2 + n2;
            const float* s = stg + n * STG_STR + lane * 8;
            float4 f0 = *reinterpret_cast<const float4*>(s);
            float4 f1 = *reinterpret_cast<const float4*>(s + 4);
            __half2 h0 = __floats2half2_rn(f0.x, f0.y);
            __half2 h1 = __floats2half2_rn(f0.z, f0.w);
            __half2 h2 = __floats2half2_rn(f1.x, f1.y);
            __half2 h3 = __floats2half2_rn(f1.z, f1.w);
            uint4 v;
            v.x = *reinterpret_cast<unsigned*>(&h0);
            v.y = *reinterpret_cast<unsigned*>(&h1);
            v.z = *reinterpret_cast<unsigned*>(&h2);
            v.w = *reinterpret_cast<unsigned*>(&h3);
            *reinterpret_cast<uint4*>(tg + (size_t)n * TSZ + off + lane * 8) = v;
        }
    }
}

template<int C, int B, int ANG, int ANGX>
__device__ __forceinline__ void fam3(const float* __restrict__ Pt,
                                     const float* __restrict__ sx,
                                     int xoff, float* __restrict__ stgA,
                                     float* __restrict__ stgB,
                                     __half* __restrict__ tg, int toff) {
    const int tid = threadIdx.x;
    const int NEH = 4 * ANG * C;
    for (int cb = 0; cb < NEH; cb += 256) {
        const int e = cb + tid;
        if (e < NEH) {
            const int c  = e % C;
            const int la = e / C;
            const int a  = la % ANG;
            const int l  = la / ANG;
            const ull* xb = reinterpret_cast<const ull*>(sx) + (xoff + a) * (NT / 2);
            ull acc0[8], acc1[8];
            #pragma unroll
            for (int np = 0; np < 8; np++) { acc0[np] = 0ull; acc1[np] = 0ull; }
            const float* PlA = Pt + (l * B) * C + c;
            const float* PlB = Pt + ((l + 4) * B) * C + c;
            #pragma unroll 1
            for (int bc = 0; bc < B; bc += 8) {
                ull pA[8], pB[8];
                #pragma unroll
                for (int j = 0; j < 8; j++) {
                    pA[j] = dup2(PlA[(bc + j) * C]);
                    pB[j] = dup2(PlB[(bc + j) * C]);
                }
                #pragma unroll
                for (int j = 0; j < 8; j++) {
                    #pragma unroll
                    for (int np = 0; np < 8; np++) {
                        ull xv = xb[(bc + j) * ANGX * 8 + np];
                        fma2(acc0[np], pA[j], xv);
                        fma2(acc1[np], pB[j], xv);
                    }
                }
            }
            #pragma unroll
            for (int np = 0; np < 8; np++) {
                float2 r0 = unpk2(acc0[np]);
                float2 r1 = unpk2(acc1[np]);
                stgA[(2 * np)     * STG_STR + tid] = r0.x;
                stgA[(2 * np + 1) * STG_STR + tid] = r0.y;
                stgB[(2 * np)     * STG_STR + tid] = r1.x;
                stgB[(2 * np + 1) * STG_STR + tid] = r1.y;
            }
        }
        __syncthreads();
        const int cols = min(256, NEH - cb);
        flush_chunk16(stgA, tg, toff + cb, cols);
        flush_chunk16(stgB, tg, toff + NEH + cb, cols);
        __syncthreads();
    }
}

__device__ __forceinline__ void stage1_body(
    const float* __restrict__ xa, const float* __restrict__ xv, const float* __restrict__ xd,
    int blk)
{
    extern __shared__ float smem[];
    float* sx   = smem;
    float* stgA = smem + SX_SZ;
    float* stgB = smem + SX_SZ + STG_HALF;
    const int node0 = blk * NT;
    const int tid = threadIdx.x;
    for (int i = tid; i < NT * 64;  i += 256) { int n = i / 64,  f = i % 64;        sx[f * 16 + n] = xa[node0 * 64  + i]; }
    for (int i = tid; i < NT * 96;  i += 256) { int n = i / 96,  f = 64 + i % 96;   sx[f * 16 + n] = xv[node0 * 96  + i]; }
    for (int i = tid; i < NT * 144; i += 256) { int n = i / 144, f = 160 + i % 144; sx[f * 16 + n] = xd[node0 * 144 + i]; }
    __syncthreads();
    __half* tg = g_t + (size_t)node0 * TSZ;
    fam3<64, 64, 1, 1>(g_Pt + T000, sx, 0,   stgA, stgB, tg, O000);
    fam3<32, 64, 1, 1>(g_Pt + T101, sx, 0,   stgA, stgB, tg, O101);
    fam3<16, 64, 1, 1>(g_Pt + T202, sx, 0,   stgA, stgB, tg, O202);
    fam3<64, 32, 3, 3>(g_Pt + T110, sx, 64,  stgA, stgB, tg, O110);
    fam3<64, 16, 9, 9>(g_Pt + T220, sx, 160, stgA, stgB, tg, O220);
    fam3<32, 32, 3, 3>(g_Pt + T011, sx, 64,  stgA, stgB, tg, O011);
    fam3<32, 16, 9, 9>(g_Pt + T121, sx, 160, stgA, stgB, tg, O121);
    fam3<32, 32, 3, 3>(g_Pt + T211, sx, 64,  stgA, stgB, tg, O211);
    fam3<32, 32, 3, 3>(g_Pt + T111, sx, 64,  stgA, stgB, tg, O111);
    fam3<16, 16, 9, 9>(g_Pt + T022, sx, 160, stgA, stgB, tg, O022);
    fam3<16, 32, 3, 3>(g_Pt + T112, sx, 64,  stgA, stgB, tg, O112);
    fam3<16, 16, 9, 9>(g_Pt + T222, sx, 160, stgA, stgB, tg, O222);
    fam3<16, 32, 3, 3>(g_Pt + T212, sx, 64,  stgA, stgB, tg, O212);
}

// ---------------- launch 3: scatterS + scatterD + stage1 fused ----------------
__global__ void __launch_bounds__(256, 2) combo_kernel(
    const int* __restrict__ src, const int* __restrict__ dst,
    const float* __restrict__ xa, const float* __restrict__ xv, const float* __restrict__ xd)
{
    if (blockIdx.x < HIST_BLOCKS) {
        int i = blockIdx.x * 256 + threadIdx.x;
        int sn = src[i];
        int p = g_startS[sn] + atomicAdd(&g_curS[sn], 1);
        g_sortS[p] = i;
    } else if (blockIdx.x < 2 * HIST_BLOCKS) {
        int i = (blockIdx.x - HIST_BLOCKS) * 256 + threadIdx.x;
        int dn = dst[i];
        int p = g_startD[dn] + atomicAdd(&g_curD[dn], 1);
        g_sortD[p] = i;
    } else {
        stage1_body(xa, xv, xd, blockIdx.x - 2 * HIST_BLOCKS);
    }
}

// ---------------- stage 2a (R11/R13 exact): per-edge contraction, fp16 smem tile ----------------

__device__ __forceinline__ void edge_geom(const float* __restrict__ rij, int e,
                                          float* rad, float* rh, float* rr) {
    const float rx = rij[3 * e + 0], ry = rij[3 * e + 1], rz = rij[3 * e + 2];
    const float xsq = (rx * rx + ry * ry + rz * rz) * 0.125f;
    const float env = fmaxf(0.f, 1.f - xsq);
    const float c1  = cosf(3.14159265358979f * sqrtf(xsq));
    rad[0] = env; rad[1] = c1 * env;
    float cm2 = 1.f, cm1 = c1;
    #pragma unroll
    for (int l = 2; l < 8; l++) {
        float cn = 2.f * c1 * cm1 - cm2;
        rad[l] = cn * env;
        cm2 = cm1; cm1 = cn;
    }
    const float vx = rx * 0.875f, vy = ry * 0.875f, vz = rz * 0.875f;
    const float nr = sqrtf(vx * vx + vy * vy + vz * vz);
    const float sc = tanhf(nr) / fmaxf(nr, 1e-6f);
    rh[0] = vx * sc; rh[1] = vy * sc; rh[2] = vz * sc;
    #pragma unroll
    for (int i = 0; i < 3; i++)
        #pragma unroll
        for (int j = 0; j < 3; j++) rr[i * 3 + j] = rh[i] * rh[j];
}

__device__ __forceinline__ float ldh(const __half* __restrict__ st, int idx) {
    return __half2float(st[idx]);
}

__global__ void __launch_bounds__(256, 4) edge_kernel(
    const float* __restrict__ rij)
{
    extern __shared__ __half st[];
    const int n   = blockIdx.x;
    const int tid = threadIdx.x;
    // raw fp16 tile copy (no conversion)
    {
        const uint4* tg = reinterpret_cast<const uint4*>(g_t + (size_t)n * TSZ);
        uint4* st4 = reinterpret_cast<uint4*>(st);
        for (int i = tid; i < TSZ / 8; i += 256) st4[i] = tg[i];
    }
    __syncthreads();
    const int s0 = g_startS[n], s1 = g_startS[n + 1];
    const int warp = tid >> 5, lane = tid & 31;
    const int c16 = lane & 15;

    for (int k = s0 + 2 * warp; k < s1; k += 16) {
        const int eA = g_sortS[k];
        const bool vB = (k + 1 < s1);
        const int eB = g_sortS[vB ? k + 1 : k];
        float* mA = g_m + (size_t)eA * OUTC;
        float* mB = g_m + (size_t)eB * OUTC;
        float radA[8], rhA[3], rrA[9], radB[8], rhB[3], rrB[9];
        edge_geom(rij, eA, radA, rhA, rrA);
        edge_geom(rij, eB, radB, rhB, rrB);

        // ---------- m_a : channels 2*lane, 2*lane+1 via half2 loads ----------
        {
            float a0A = 0.f, a1A = 0.f, a0B = 0.f, a1B = 0.f;
            #pragma unroll
            for (int l = 0; l < 8; l++) {
                const float2 p0 = __half22float2(*reinterpret_cast<const __half2*>(st + O000 + l * 64 + 2 * lane));
                float sxA = p0.x, syA = p0.y, sxB = p0.x, syB = p0.y;
                #pragma unroll
                for (int i = 0; i < 3; i++) {
                    const float2 p = __half22float2(*reinterpret_cast<const __half2*>(st + O110 + (l * 3 + i) * 64 + 2 * lane));
                    sxA += rhA[i] * p.x; syA += rhA[i] * p.y;
                    sxB += rhB[i] * p.x; syB += rhB[i] * p.y;
                }
                #pragma unroll
                for (int a = 0; a < 9; a++) {
                    const float2 p = __half22float2(*reinterpret_cast<const __half2*>(st + O220 + (l * 9 + a) * 64 + 2 * lane));
                    sxA += rrA[a] * p.x; syA += rrA[a] * p.y;
                    sxB += rrB[a] * p.x; syB += rrB[a] * p.y;
                }
                a0A += radA[l] * sxA; a1A += radA[l] * syA;
                a0B += radB[l] * sxB; a1B += radB[l] * syB;
            }
            *reinterpret_cast<float2*>(mA + 2 * lane) = make_float2(a0A, a1A);
            if (vB) *reinterpret_cast<float2*>(mB + 2 * lane) = make_float2(a0B, a1B);
        }

        // ---------- m_v : channel c = lane ----------
        {
            float vA[3] = {0, 0, 0}, uA[3] = {0, 0, 0}, SA = 0.f;
            float vB3[3] = {0, 0, 0}, uB[3] = {0, 0, 0}, SB = 0.f;
            #pragma unroll
            for (int l = 0; l < 8; l++) {
                float t011[3], t211[3], t111[3], t121[9];
                const float t101 = ldh(st, O101 + l * 32 + lane);
                #pragma unroll
                for (int i = 0; i < 3; i++) {
                    t011[i] = ldh(st, O011 + (l * 3 + i) * 32 + lane);
                    t211[i] = ldh(st, O211 + (l * 3 + i) * 32 + lane);
                    t111[i] = ldh(st, O111 + (l * 3 + i) * 32 + lane);
                }
                #pragma unroll
                for (int a = 0; a < 9; a++) t121[a] = ldh(st, O121 + (l * 9 + a) * 32 + lane);

                float sSA = t101, sSB = t101;
                #pragma unroll
                for (int j = 0; j < 3; j++) { sSA += rhA[j] * t211[j]; sSB += rhB[j] * t211[j]; }
                SA += radA[l] * sSA; SB += radB[l] * sSB;
                #pragma unroll
                for (int i = 0; i < 3; i++) {
                    float svA = t011[i], svB = t011[i];
                    #pragma unroll
                    for (int j = 0; j < 3; j++) {
                        svA += rhA[j] * t121[i * 3 + j];
                        svB += rhB[j] * t121[i * 3 + j];
                    }
                    vA[i]  += radA[l] * svA;
                    vB3[i] += radB[l] * svB;
                    uA[i]  += radA[l] * t111[i];
                    uB[i]  += radB[l] * t111[i];
                }
            }
            vA[0]  += SA * rhA[0] + (rhA[1] * uA[2] - rhA[2] * uA[1]);
            vA[1]  += SA * rhA[1] + (rhA[2] * uA[0] - rhA[0] * uA[2]);
            vA[2]  += SA * rhA[2] + (rhA[0] * uA[1] - rhA[1] * uA[0]);
            vB3[0] += SB * rhB[0] + (rhB[1] * uB[2] - rhB[2] * uB[1]);
            vB3[1] += SB * rhB[1] + (rhB[2] * uB[0] - rhB[0] * uB[2]);
            vB3[2] += SB * rhB[2] + (rhB[0] * uB[1] - rhB[1] * uB[0]);
            #pragma unroll
            for (int i = 0; i < 3; i++) mA[64 + lane * 3 + i] = vA[i];
            if (vB) {
                #pragma unroll
                for (int i = 0; i < 3; i++) mB[64 + lane * 3 + i] = vB3[i];
            }
        }

        // ---------- m_d : c = lane&15, half-warps split the l-sum ----------
        {
            const int hh = lane >> 4;
            float radhA[4], radhB[4];
            #pragma unroll
            for (int i = 0; i < 4; i++) {
                radhA[i] = (hh == 0) ? radA[i] : radA[4 + i];
                radhB[i] = (hh == 0) ? radB[i] : radB[4 + i];
            }
            float outA[9] = {0,0,0,0,0,0,0,0,0};
            float outB[9] = {0,0,0,0,0,0,0,0,0};
            #pragma unroll
            for (int ll = 0; ll < 4; ll++) {
                const int l = hh * 4 + ll;
                float t022[9], t222[9], t112[3], t212[3];
                const float t202 = ldh(st, O202 + l * 16 + c16);
                #pragma unroll
                for (int a = 0; a < 9; a++) {
                    t022[a] = ldh(st, O022 + (l * 9 + a) * 16 + c16);
                    t222[a] = ldh(st, O222 + (l * 9 + a) * 16 + c16);
                }
                #pragma unroll
                for (int j = 0; j < 3; j++) {
                    t112[j] = ldh(st, O112 + (l * 3 + j) * 16 + c16);
                    t212[j] = ldh(st, O212 + (l * 3 + j) * 16 + c16);
                }
                float qA[3], qB[3];
                #pragma unroll
                for (int j = 0; j < 3; j++) {
                    qA[j] = t112[j] + rhA[0] * t222[j] + rhA[1] * t222[3 + j] + rhA[2] * t222[6 + j];
                    qB[j] = t112[j] + rhB[0] * t222[j] + rhB[1] * t222[3 + j] + rhB[2] * t222[6 + j];
                }
                qA[0] += rhA[1] * t212[2] - rhA[2] * t212[1];
                qA[1] += rhA[2] * t212[0] - rhA[0] * t212[2];
                qA[2] += rhA[0] * t212[1] - rhA[1] * t212[0];
                qB[0] += rhB[1] * t212[2] - rhB[2] * t212[1];
                qB[1] += rhB[2] * t212[0] - rhB[0] * t212[2];
                qB[2] += rhB[0] * t212[1] - rhB[1] * t212[0];
                #pragma unroll
                for (int ij = 0; ij < 9; ij++) {
                    const int i = ij / 3, j = ij % 3;
                    outA[ij] += radhA[ll] * (t022[ij] + rrA[ij] * t202 + rhA[i] * qA[j]);
                    outB[ij] += radhB[ll] * (t022[ij] + rrB[ij] * t202 + rhB[i] * qB[j]);
                }
            }
            #pragma unroll
            for (int ij = 0; ij < 9; ij++) {
                outA[ij] += __shfl_xor_sync(0xffffffffu, outA[ij], 16);
                outB[ij] += __shfl_xor_sync(0xffffffffu, outB[ij], 16);
            }
            #pragma unroll
            for (int ij = 0; ij < 9; ij++) {
                const bool mine = (hh == 0) ? (ij < 5) : (ij >= 5);
                if (mine) {
                    mA[160 + c16 * 9 + ij] = outA[ij];
                    if (vB) mB[160 + c16 * 9 + ij] = outB[ij];
                }
            }
        }
    }
}

// ---------------- launch 5: dst-grouped segment sum ----------------
__global__ void __launch_bounds__(256) gather_kernel(float* __restrict__ out) {
    const int warp = threadIdx.x >> 5, lane = threadIdx.x & 31;
    const int node = blockIdx.x * 8 + warp;
    float4 acc0 = make_float4(0, 0, 0, 0);
    float4 acc1 = make_float4(0, 0, 0, 0);
    float4 acc2 = make_float4(0, 0, 0, 0);
    const int q0 = lane, q1 = lane + 32, q2 = lane + 64;
    const int s0 = g_startD[node], s1 = g_startD[node + 1];
    for (int k = s0; k < s1; k++) {
        const int e = g_sortD[k];
        const float4* row = reinterpret_cast<const float4*>(g_m + (size_t)e * OUTC);
        float4 r0 = row[q0];
        float4 r1 = row[q1];
        acc0.x += r0.x; acc0.y += r0.y; acc0.z += r0.z; acc0.w += r0.w;
        acc1.x += r1.x; acc1.y += r1.y; acc1.z += r1.z; acc1.w += r1.w;
        if (lane < 12) {
            float4 r2 = row[q2];
            acc2.x += r2.x; acc2.y += r2.y; acc2.z += r2.z; acc2.w += r2.w;
        }
    }
    float4* orow = reinterpret_cast<float4*>(out + (size_t)node * OUTC);
    orow[q0] = acc0;
    orow[q1] = acc1;
    if (lane < 12) orow[q2] = acc2;

    const int gt = blockIdx.x * 256 + threadIdx.x;
    if (gt < NODES) { g_cntS[gt] = 0; g_curS[gt] = 0; g_cntD[gt] = 0; g_curD[gt] = 0; }
}

extern "C" void kernel_launch(void* const* d_in, const int* in_sizes, int n_in,
                              void* d_out, int out_size) {
    const float* x_a  = (const float*)d_in[0];
    const float* x_v  = (const float*)d_in[1];
    const float* x_d  = (const float*)d_in[2];
    const float* rij  = (const float*)d_in[3];
    const float* P000 = (const float*)d_in[4];
    const float* P110 = (const float*)d_in[5];
    const float* P220 = (const float*)d_in[6];
    const float* P011 = (const float*)d_in[7];
    const float* P101 = (const float*)d_in[8];
    const float* P121 = (const float*)d_in[9];
    const float* P211 = (const float*)d_in[10];
    const float* P111 = (const float*)d_in[11];
    const float* P022 = (const float*)d_in[12];
    const float* P112 = (const float*)d_in[13];
    const float* P202 = (const float*)d_in[14];
    const float* P222 = (const float*)d_in[15];
    const float* P212 = (const float*)d_in[16];
    const int*   src  = (const int*)d_in[17];
    const int*   dst  = (const int*)d_in[18];
    float* out = (float*)d_out;

    cudaFuncSetAttribute(combo_kernel, cudaFuncAttributeMaxDynamicSharedMemorySize, S1_SMEM);
    cudaFuncSetAttribute(edge_kernel,  cudaFuncAttributeMaxDynamicSharedMemorySize, TSZ * 2);

    // 1: histS + histD + P-transpose
    prep_kernel<<<2 * HIST_BLOCKS + TP_BLOCKS, 256>>>(src, dst,
                                                      P000, P110, P220, P011, P101,
                                                      P121, P211, P111, P022, P112,
                                                      P202, P222, P212);
    // 2: both scans
    scan2_kernel<<<2, 1024>>>();
    // 3: scatterS + scatterD + stage1
    combo_kernel<<<2 * HIST_BLOCKS + S1_BLOCKS, 256, S1_SMEM>>>(src, dst, x_a, x_v, x_d);
    // 4: edge  <-- ncu capture slot
    edge_kernel<<<NODES, 256, TSZ * 2>>>(rij);
    // 5: gather
    gather_kernel<<<NODES / 8, 256>>>(out);
}

// round 16
// speedup vs baseline: 2.2448x; 1.0595x over previous
#include <cuda_runtime.h>
#include <cuda_fp16.h>
#include <math.h>

#define NODES 16384
#define EDGES 262144
#define TSZ   13184
#define OUTC  304

// per-node t layout offsets (half elements), all [l][ang][c], c fastest
// family 220 is symmetrized: ANG=6 (a6: 00,11,22,01,02,12)
#define O000  0
#define O110  512
#define O220  2048
#define O011  5120
#define O101  5888
#define O121  6144
#define O211  8448
#define O111  9216
#define O022  9984
#define O112  11136
#define O202  11520
#define O222  11648
#define O212  12800

// transposed-P offsets in g_Pt (floats), layout [l][b][c] per family
#define T000  0
#define T110  32768
#define T220  49152
#define T011  57344
#define T101  65536
#define T121  81920
#define T211  86016
#define T111  94208
#define T022  102400
#define T112  104448
#define T202  108544
#define T222  116736
#define T212  118784
#define TPTOT 122880

#define NT 16                        // nodes per stage1 block
#define SX_SZ   (400 * NT)           // floats: 304 base features + 96 symmetrized xd
#define STG_STR 260                  // floats per node row in staging
#define STG_HALF (NT * STG_STR)
#define S1_SMEM ((SX_SZ + 2 * STG_HALF) * 4)

#define HIST_BLOCKS  (EDGES / 256)   // 1024
#define TP_BLOCKS    (TPTOT / 256 + 1)
#define S1_BLOCKS    (NODES / NT)    // 1024

typedef unsigned long long ull;

__device__ __half g_t[(size_t)NODES * TSZ];           // 432 MB scratch (fp16)
__device__ float  g_m[(size_t)EDGES * OUTC];          // 319 MB per-edge messages
__device__ float  g_Pt[TPTOT];                        // transposed P, c-fastest
__device__ int g_cntS[NODES], g_curS[NODES], g_startS[NODES + 1], g_sortS[EDGES];
__device__ int g_cntD[NODES], g_curD[NODES], g_startD[NODES + 1], g_sortD[EDGES];

// ---- packed f32x2 helpers ----
__device__ __forceinline__ ull dup2(float x) {
    ull r; asm("mov.b64 %0, {%1, %1};" : "=l"(r) : "f"(x)); return r;
}
__device__ __forceinline__ void fma2(ull& a, ull b, ull c) {
    asm("fma.rn.f32x2 %0, %1, %2, %0;" : "+l"(a) : "l"(b), "l"(c));
}
__device__ __forceinline__ float2 unpk2(ull a) {
    float2 f; asm("mov.b64 {%0, %1}, %2;" : "=f"(f.x), "=f"(f.y) : "l"(a)); return f;
}

// ---------------- P transpose helper: P[c][l][b] -> Pt[l][b][c] ----------------
__device__ __forceinline__ void tp1(const float* __restrict__ P, float* __restrict__ Pt,
                                    int i, int C, int B) {
    const int b = i % B;
    const int l = (i / B) % 8;
    const int c = i / (8 * B);
    Pt[(l * B + b) * C + c] = P[i];
}

// ---------------- launch 1: histS + histD + transpose fused ----------------
__global__ void prep_kernel(
    const int* __restrict__ src, const int* __restrict__ dst,
    const float* __restrict__ P000, const float* __restrict__ P110, const float* __restrict__ P220,
    const float* __restrict__ P011, const float* __restrict__ P101, const float* __restrict__ P121,
    const float* __restrict__ P211, const float* __restrict__ P111, const float* __restrict__ P022,
    const float* __restrict__ P112, const float* __restrict__ P202, const float* __restrict__ P222,
    const float* __restrict__ P212)
{
    if (blockIdx.x < HIST_BLOCKS) {
        int i = blockIdx.x * 256 + threadIdx.x;
        atomicAdd(&g_cntS[src[i]], 1);
    } else if (blockIdx.x < 2 * HIST_BLOCKS) {
        int i = (blockIdx.x - HIST_BLOCKS) * 256 + threadIdx.x;
        atomicAdd(&g_cntD[dst[i]], 1);
    } else {
        int i = (blockIdx.x - 2 * HIST_BLOCKS) * 256 + threadIdx.x;
        if      (i < T110)  tp1(P000, g_Pt + T000, i - T000, 64, 64);
        else if (i < T220)  tp1(P110, g_Pt + T110, i - T110, 64, 32);
        else if (i < T011)  tp1(P220, g_Pt + T220, i - T220, 64, 16);
        else if (i < T101)  tp1(P011, g_Pt + T011, i - T011, 32, 32);
        else if (i < T121)  tp1(P101, g_Pt + T101, i - T101, 32, 64);
        else if (i < T211)  tp1(P121, g_Pt + T121, i - T121, 32, 16);
        else if (i < T111)  tp1(P211, g_Pt + T211, i - T211, 32, 32);
        else if (i < T022)  tp1(P111, g_Pt + T111, i - T111, 32, 32);
        else if (i < T112)  tp1(P022, g_Pt + T022, i - T022, 16, 16);
        else if (i < T202)  tp1(P112, g_Pt + T112, i - T112, 16, 32);
        else if (i < T222)  tp1(P202, g_Pt + T202, i - T202, 16, 64);
        else if (i < T212)  tp1(P222, g_Pt + T222, i - T222, 16, 16);
        else if (i < TPTOT) tp1(P212, g_Pt + T212, i - T212, 16, 32);
    }
}

// ---------------- launch 2: both scans, one kernel ----------------
__device__ __forceinline__ void scan_body(const int* __restrict__ cnt, int* __restrict__ start) {
    __shared__ int ssum[1024];
    int t = threadIdx.x;
    int loc[16];
    int s = 0;
    int base = t * 16;
    #pragma unroll
    for (int i = 0; i < 16; i++) { loc[i] = s; s += cnt[base + i]; }
    ssum[t] = s;
    __syncthreads();
    for (int off = 1; off < 1024; off <<= 1) {
        int v = (t >= off) ? ssum[t - off] : 0;
        __syncthreads();
        if (t >= off) ssum[t] += v;
        __syncthreads();
    }
    int excl = (t == 0) ? 0 : ssum[t - 1];
    #pragma unroll
    for (int i = 0; i < 16; i++) start[base + i] = excl + loc[i];
    if (t == 0) start[NODES] = EDGES;
}

__global__ void scan2_kernel() {
    if (blockIdx.x == 0) scan_body(g_cntS, g_startS);
    else                 scan_body(g_cntD, g_startD);
}

// ---------------- stage 1: f32x2, l-paired, staged flush (220 symmetrized) ----------------

__device__ __forceinline__ void flush_chunk16(const float* __restrict__ stg,
                                              __half* __restrict__ tg,
                                              int off, int cols) {
    const int warp = threadIdx.x >> 5, lane = threadIdx.x & 31;
    if (lane * 8 < cols) {
        #pragma unroll
        for (int n2 = 0; n2 < 2; n2++) {
            const int n = warp * 2 + n2;
            const float* s = stg + n * STG_STR + lane * 8;
            float4 f0 = *reinterpret_cast<const float4*>(s);
            float4 f1 = *reinterpret_cast<const float4*>(s + 4);
            __half2 h0 = __floats2half2_rn(f0.x, f0.y);
            __half2 h1 = __floats2half2_rn(f0.z, f0.w);
            __half2 h2 = __floats2half2_rn(f1.x, f1.y);
            __half2 h3 = __floats2half2_rn(f1.z, f1.w);
            uint4 v;
            v.x = *reinterpret_cast<unsigned*>(&h0);
            v.y = *reinterpret_cast<unsigned*>(&h1);
            v.z = *reinterpret_cast<unsigned*>(&h2);
            v.w = *reinterpret_cast<unsigned*>(&h3);
            *reinterpret_cast<uint4*>(tg + (size_t)n * TSZ + off + lane * 8) = v;
        }
    }
}

template<int C, int B, int ANG, int ANGX>
__device__ __forceinline__ void fam3(const float* __restrict__ Pt,
                                     const float* __restrict__ sx,
                                     int xoff, float* __restrict__ stgA,
                                     float* __restrict__ stgB,
                                     __half* __restrict__ tg, int toff) {
    const int tid = threadIdx.x;
    const int NEH = 4 * ANG * C;
    for (int cb = 0; cb < NEH; cb += 256) {
        const int e = cb + tid;
        if (e < NEH) {
            const int c  = e % C;
            const int la = e / C;
            const int a  = la % ANG;
            const int l  = la / ANG;
            const ull* xb = reinterpret_cast<const ull*>(sx) + (xoff + a) * (NT / 2);
            ull acc0[8], acc1[8];
            #pragma unroll
            for (int np = 0; np < 8; np++) { acc0[np] = 0ull; acc1[np] = 0ull; }
            const float* PlA = Pt + (l * B) * C + c;
            const float* PlB = Pt + ((l + 4) * B) * C + c;
            #pragma unroll 1
            for (int bc = 0; bc < B; bc += 8) {
                ull pA[8], pB[8];
                #pragma unroll
                for (int j = 0; j < 8; j++) {
                    pA[j] = dup2(PlA[(bc + j) * C]);
                    pB[j] = dup2(PlB[(bc + j) * C]);
                }
                #pragma unroll
                for (int j = 0; j < 8; j++) {
                    #pragma unroll
                    for (int np = 0; np < 8; np++) {
                        ull xv = xb[(bc + j) * ANGX * 8 + np];
                        fma2(acc0[np], pA[j], xv);
                        fma2(acc1[np], pB[j], xv);
                    }
                }
            }
            #pragma unroll
            for (int np = 0; np < 8; np++) {
                float2 r0 = unpk2(acc0[np]);
                float2 r1 = unpk2(acc1[np]);
                stgA[(2 * np)     * STG_STR + tid] = r0.x;
                stgA[(2 * np + 1) * STG_STR + tid] = r0.y;
                stgB[(2 * np)     * STG_STR + tid] = r1.x;
                stgB[(2 * np + 1) * STG_STR + tid] = r1.y;
            }
        }
        __syncthreads();
        const int cols = min(256, NEH - cb);
        flush_chunk16(stgA, tg, toff + cb, cols);
        flush_chunk16(stgB, tg, toff + NEH + cb, cols);
        __syncthreads();
    }
}

__device__ __forceinline__ void stage1_body(
    const float* __restrict__ xa, const float* __restrict__ xv, const float* __restrict__ xd,
    int blk)
{
    extern __shared__ float smem[];
    float* sx   = smem;
    float* stgA = smem + SX_SZ;
    float* stgB = smem + SX_SZ + STG_HALF;
    const int node0 = blk * NT;
    const int tid = threadIdx.x;
    for (int i = tid; i < NT * 64;  i += 256) { int n = i / 64,  f = i % 64;        sx[f * 16 + n] = xa[node0 * 64  + i]; }
    for (int i = tid; i < NT * 96;  i += 256) { int n = i / 96,  f = 64 + i % 96;   sx[f * 16 + n] = xv[node0 * 96  + i]; }
    for (int i = tid; i < NT * 144; i += 256) { int n = i / 144, f = 160 + i % 144; sx[f * 16 + n] = xd[node0 * 144 + i]; }
    // symmetrized xd: f = 304 + b*6 + a6, a6: {00,11,22,01,02,12}; offdiag = xd[ij]+xd[ji]
    for (int i = tid; i < NT * 96; i += 256) {
        const int n = i / 96, f6 = i % 96, b = f6 / 6, a6 = f6 % 6;
        const int ii6[6] = {0, 1, 2, 0, 0, 1};
        const int jj6[6] = {0, 1, 2, 1, 2, 2};
        const float* xdn = xd + (size_t)(node0 + n) * 144 + b * 9;
        float v = xdn[ii6[a6] * 3 + jj6[a6]];
        if (a6 >= 3) v += xdn[jj6[a6] * 3 + ii6[a6]];
        sx[(304 + f6) * 16 + n] = v;
    }
    __syncthreads();
    __half* tg = g_t + (size_t)node0 * TSZ;
    fam3<64, 64, 1, 1>(g_Pt + T000, sx, 0,   stgA, stgB, tg, O000);
    fam3<32, 64, 1, 1>(g_Pt + T101, sx, 0,   stgA, stgB, tg, O101);
    fam3<16, 64, 1, 1>(g_Pt + T202, sx, 0,   stgA, stgB, tg, O202);
    fam3<64, 32, 3, 3>(g_Pt + T110, sx, 64,  stgA, stgB, tg, O110);
    fam3<64, 16, 6, 6>(g_Pt + T220, sx, 304, stgA, stgB, tg, O220);   // symmetrized
    fam3<32, 32, 3, 3>(g_Pt + T011, sx, 64,  stgA, stgB, tg, O011);
    fam3<32, 16, 9, 9>(g_Pt + T121, sx, 160, stgA, stgB, tg, O121);
    fam3<32, 32, 3, 3>(g_Pt + T211, sx, 64,  stgA, stgB, tg, O211);
    fam3<32, 32, 3, 3>(g_Pt + T111, sx, 64,  stgA, stgB, tg, O111);
    fam3<16, 16, 9, 9>(g_Pt + T022, sx, 160, stgA, stgB, tg, O022);
    fam3<16, 32, 3, 3>(g_Pt + T112, sx, 64,  stgA, stgB, tg, O112);
    fam3<16, 16, 9, 9>(g_Pt + T222, sx, 160, stgA, stgB, tg, O222);
    fam3<16, 32, 3, 3>(g_Pt + T212, sx, 64,  stgA, stgB, tg, O212);
}

// ---------------- launch 3: scatterS + scatterD + stage1 fused ----------------
__global__ void __launch_bounds__(256, 2) combo_kernel(
    const int* __restrict__ src, const int* __restrict__ dst,
    const float* __restrict__ xa, const float* __restrict__ xv, const float* __restrict__ xd)
{
    if (blockIdx.x < HIST_BLOCKS) {
        int i = blockIdx.x * 256 + threadIdx.x;
        int sn = src[i];
        int p = g_startS[sn] + atomicAdd(&g_curS[sn], 1);
        g_sortS[p] = i;
    } else if (blockIdx.x < 2 * HIST_BLOCKS) {
        int i = (blockIdx.x - HIST_BLOCKS) * 256 + threadIdx.x;
        int dn = dst[i];
        int p = g_startD[dn] + atomicAdd(&g_curD[dn], 1);
        g_sortD[p] = i;
    } else {
        stage1_body(xa, xv, xd, blockIdx.x - 2 * HIST_BLOCKS);
    }
}

// ---------------- stage 2a: per-edge contraction, fp16 smem tile ----------------

__device__ __forceinline__ void edge_geom(const float* __restrict__ rij, int e,
                                          float* rad, float* rh, float* rr) {
    const float rx = rij[3 * e + 0], ry = rij[3 * e + 1], rz = rij[3 * e + 2];
    const float xsq = (rx * rx + ry * ry + rz * rz) * 0.125f;
    const float env = fmaxf(0.f, 1.f - xsq);
    const float c1  = cosf(3.14159265358979f * sqrtf(xsq));
    rad[0] = env; rad[1] = c1 * env;
    float cm2 = 1.f, cm1 = c1;
    #pragma unroll
    for (int l = 2; l < 8; l++) {
        float cn = 2.f * c1 * cm1 - cm2;
        rad[l] = cn * env;
        cm2 = cm1; cm1 = cn;
    }
    const float vx = rx * 0.875f, vy = ry * 0.875f, vz = rz * 0.875f;
    const float nr = sqrtf(vx * vx + vy * vy + vz * vz);
    const float sc = tanhf(nr) / fmaxf(nr, 1e-6f);
    rh[0] = vx * sc; rh[1] = vy * sc; rh[2] = vz * sc;
    #pragma unroll
    for (int i = 0; i < 3; i++)
        #pragma unroll
        for (int j = 0; j < 3; j++) rr[i * 3 + j] = rh[i] * rh[j];
}

__device__ __forceinline__ float ldh(const __half* __restrict__ st, int idx) {
    return __half2float(st[idx]);
}

__global__ void __launch_bounds__(256, 4) edge_kernel(
    const float* __restrict__ rij)
{
    extern __shared__ __half st[];
    const int n   = blockIdx.x;
    const int tid = threadIdx.x;
    // raw fp16 tile copy (no conversion)
    {
        const uint4* tg = reinterpret_cast<const uint4*>(g_t + (size_t)n * TSZ);
        uint4* st4 = reinterpret_cast<uint4*>(st);
        for (int i = tid; i < TSZ / 8; i += 256) st4[i] = tg[i];
    }
    __syncthreads();
    const int s0 = g_startS[n], s1 = g_startS[n + 1];
    const int warp = tid >> 5, lane = tid & 31;
    const int c16 = lane & 15;

    for (int k = s0 + 2 * warp; k < s1; k += 16) {
        const int eA = g_sortS[k];
        const bool vB = (k + 1 < s1);
        const int eB = g_sortS[vB ? k + 1 : k];
        float* mA = g_m + (size_t)eA * OUTC;
        float* mB = g_m + (size_t)eB * OUTC;
        float radA[8], rhA[3], rrA[9], radB[8], rhB[3], rrB[9];
        edge_geom(rij, eA, radA, rhA, rrA);
        edge_geom(rij, eB, radB, rhB, rrB);

        // ---------- m_a : channels 2*lane, 2*lane+1 via half2 loads (220 symmetrized) ----------
        {
            float a0A = 0.f, a1A = 0.f, a0B = 0.f, a1B = 0.f;
            #pragma unroll
            for (int l = 0; l < 8; l++) {
                const float2 p0 = __half22float2(*reinterpret_cast<const __half2*>(st + O000 + l * 64 + 2 * lane));
                float sxA = p0.x, syA = p0.y, sxB = p0.x, syB = p0.y;
                #pragma unroll
                for (int i = 0; i < 3; i++) {
                    const float2 p = __half22float2(*reinterpret_cast<const __half2*>(st + O110 + (l * 3 + i) * 64 + 2 * lane));
                    sxA += rhA[i] * p.x; syA += rhA[i] * p.y;
                    sxB += rhB[i] * p.x; syB += rhB[i] * p.y;
                }
                #pragma unroll
                for (int a = 0; a < 6; a++) {
                    const int map6[6] = {0, 4, 8, 1, 2, 5};   // rr index per a6
                    const int m = map6[a];
                    const float2 p = __half22float2(*reinterpret_cast<const __half2*>(st + O220 + (l * 6 + a) * 64 + 2 * lane));
                    sxA += rrA[m] * p.x; syA += rrA[m] * p.y;
                    sxB += rrB[m] * p.x; syB += rrB[m] * p.y;
                }
                a0A += radA[l] * sxA; a1A += radA[l] * syA;
                a0B += radB[l] * sxB; a1B += radB[l] * syB;
            }
            *reinterpret_cast<float2*>(mA + 2 * lane) = make_float2(a0A, a1A);
            if (vB) *reinterpret_cast<float2*>(mB + 2 * lane) = make_float2(a0B, a1B);
        }

        // ---------- m_v : channel c = lane ----------
        {
            float vA[3] = {0, 0, 0}, uA[3] = {0, 0, 0}, SA = 0.f;
            float vB3[3] = {0, 0, 0}, uB[3] = {0, 0, 0}, SB = 0.f;
            #pragma unroll
            for (int l = 0; l < 8; l++) {
                float t011[3], t211[3], t111[3], t121[9];
                const float t101 = ldh(st, O101 + l * 32 + lane);
                #pragma unroll
                for (int i = 0; i < 3; i++) {
                    t011[i] = ldh(st, O011 + (l * 3 + i) * 32 + lane);
                    t211[i] = ldh(st, O211 + (l * 3 + i) * 32 + lane);
                    t111[i] = ldh(st, O111 + (l * 3 + i) * 32 + lane);
                }
                #pragma unroll
                for (int a = 0; a < 9; a++) t121[a] = ldh(st, O121 + (l * 9 + a) * 32 + lane);

                float sSA = t101, sSB = t101;
                #pragma unroll
                for (int j = 0; j < 3; j++) { sSA += rhA[j] * t211[j]; sSB += rhB[j] * t211[j]; }
                SA += radA[l] * sSA; SB += radB[l] * sSB;
                #pragma unroll
                for (int i = 0; i < 3; i++) {
                    float svA = t011[i], svB = t011[i];
                    #pragma unroll
                    for (int j = 0; j < 3; j++) {
                        svA += rhA[j] * t121[i * 3 + j];
                        svB += rhB[j] * t121[i * 3 + j];
                    }
                    vA[i]  += radA[l] * svA;
                    vB3[i] += radB[l] * svB;
                    uA[i]  += radA[l] * t111[i];
                    uB[i]  += radB[l] * t111[i];
                }
            }
            vA[0]  += SA * rhA[0] + (rhA[1] * uA[2] - rhA[2] * uA[1]);
            vA[1]  += SA * rhA[1] + (rhA[2] * uA[0] - rhA[0] * uA[2]);
            vA[2]  += SA * rhA[2] + (rhA[0] * uA[1] - rhA[1] * uA[0]);
            vB3[0] += SB * rhB[0] + (rhB[1] * uB[2] - rhB[2] * uB[1]);
            vB3[1] += SB * rhB[1] + (rhB[2] * uB[0] - rhB[0] * uB[2]);
            vB3[2] += SB * rhB[2] + (rhB[0] * uB[1] - rhB[1] * uB[0]);
            #pragma unroll
            for (int i = 0; i < 3; i++) mA[64 + lane * 3 + i] = vA[i];
            if (vB) {
                #pragma unroll
                for (int i = 0; i < 3; i++) mB[64 + lane * 3 + i] = vB3[i];
            }
        }

        // ---------- m_d : c = lane&15, half-warps split the l-sum ----------
        {
            const int hh = lane >> 4;
            float radhA[4], radhB[4];
            #pragma unroll
            for (int i = 0; i < 4; i++) {
                radhA[i] = (hh == 0) ? radA[i] : radA[4 + i];
                radhB[i] = (hh == 0) ? radB[i] : radB[4 + i];
            }
            float outA[9] = {0,0,0,0,0,0,0,0,0};
            float outB[9] = {0,0,0,0,0,0,0,0,0};
            #pragma unroll
            for (int ll = 0; ll < 4; ll++) {
                const int l = hh * 4 + ll;
                float t022[9], t222[9], t112[3], t212[3];
                const float t202 = ldh(st, O202 + l * 16 + c16);
                #pragma unroll
                for (int a = 0; a < 9; a++) {
                    t022[a] = ldh(st, O022 + (l * 9 + a) * 16 + c16);
                    t222[a] = ldh(st, O222 + (l * 9 + a) * 16 + c16);
                }
                #pragma unroll
                for (int j = 0; j < 3; j++) {
                    t112[j] = ldh(st, O112 + (l * 3 + j) * 16 + c16);
                    t212[j] = ldh(st, O212 + (l * 3 + j) * 16 + c16);
                }
                float qA[3], qB[3];
                #pragma unroll
                for (int j = 0; j < 3; j++) {
                    qA[j] = t112[j] + rhA[0] * t222[j] + rhA[1] * t222[3 + j] + rhA[2] * t222[6 + j];
                    qB[j] = t112[j] + rhB[0] * t222[j] + rhB[1] * t222[3 + j] + rhB[2] * t222[6 + j];
                }
                qA[0] += rhA[1] * t212[2] - rhA[2] * t212[1];
                qA[1] += rhA[2] * t212[0] - rhA[0] * t212[2];
                qA[2] += rhA[0] * t212[1] - rhA[1] * t212[0];
                qB[0] += rhB[1] * t212[2] - rhB[2] * t212[1];
                qB[1] += rhB[2] * t212[0] - rhB[0] * t212[2];
                qB[2] += rhB[0] * t212[1] - rhB[1] * t212[0];
                #pragma unroll
                for (int ij = 0; ij < 9; ij++) {
                    const int i = ij / 3, j = ij % 3;
                    outA[ij] += radhA[ll] * (t022[ij] + rrA[ij] * t202 + rhA[i] * qA[j]);
                    outB[ij] += radhB[ll] * (t022[ij] + rrB[ij] * t202 + rhB[i] * qB[j]);
                }
            }
            #pragma unroll
            for (int ij = 0; ij < 9; ij++) {
                outA[ij] += __shfl_xor_sync(0xffffffffu, outA[ij], 16);
                outB[ij] += __shfl_xor_sync(0xffffffffu, outB[ij], 16);
            }
            #pragma unroll
            for (int ij = 0; ij < 9; ij++) {
                const bool mine = (hh == 0) ? (ij < 5) : (ij >= 5);
                if (mine) {
                    mA[160 + c16 * 9 + ij] = outA[ij];
                    if (vB) mB[160 + c16 * 9 + ij] = outB[ij];
                }
            }
        }
    }
}

// ---------------- launch 5: dst-grouped segment sum ----------------
__global__ void __launch_bounds__(256) gather_kernel(float* __restrict__ out) {
    const int warp = threadIdx.x >> 5, lane = threadIdx.x & 31;
    const int node = blockIdx.x * 8 + warp;
    float4 acc0 = make_float4(0, 0, 0, 0);
    float4 acc1 = make_float4(0, 0, 0, 0);
    float4 acc2 = make_float4(0, 0, 0, 0);
    const int q0 = lane, q1 = lane + 32, q2 = lane + 64;
    const int s0 = g_startD[node], s1 = g_startD[node + 1];
    for (int k = s0; k < s1; k++) {
        const int e = g_sortD[k];
        const float4* row = reinterpret_cast<const float4*>(g_m + (size_t)e * OUTC);
        float4 r0 = row[q0];
        float4 r1 = row[q1];
        acc0.x += r0.x; acc0.y += r0.y; acc0.z += r0.z; acc0.w += r0.w;
        acc1.x += r1.x; acc1.y += r1.y; acc1.z += r1.z; acc1.w += r1.w;
        if (lane < 12) {
            float4 r2 = row[q2];
            acc2.x += r2.x; acc2.y += r2.y; acc2.z += r2.z; acc2.w += r2.w;
        }
    }
    float4* orow = reinterpret_cast<float4*>(out + (size_t)node * OUTC);
    orow[q0] = acc0;
    orow[q1] = acc1;
    if (lane < 12) orow[q2] = acc2;

    const int gt = blockIdx.x * 256 + threadIdx.x;
    if (gt < NODES) { g_cntS[gt] = 0; g_curS[gt] = 0; g_cntD[gt] = 0; g_curD[gt] = 0; }
}

extern "C" void kernel_launch(void* const* d_in, const int* in_sizes, int n_in,
                              void* d_out, int out_size) {
    const float* x_a  = (const float*)d_in[0];
    const float* x_v  = (const float*)d_in[1];
    const float* x_d  = (const float*)d_in[2];
    const float* rij  = (const float*)d_in[3];
    const float* P000 = (const float*)d_in[4];
    const float* P110 = (const float*)d_in[5];
    const float* P220 = (const float*)d_in[6];
    const float* P011 = (const float*)d_in[7];
    const float* P101 = (const float*)d_in[8];
    const float* P121 = (const float*)d_in[9];
    const float* P211 = (const float*)d_in[10];
    const float* P111 = (const float*)d_in[11];
    const float* P022 = (const float*)d_in[12];
    const float* P112 = (const float*)d_in[13];
    const float* P202 = (const float*)d_in[14];
    const float* P222 = (const float*)d_in[15];
    const float* P212 = (const float*)d_in[16];
    const int*   src  = (const int*)d_in[17];
    const int*   dst  = (const int*)d_in[18];
    float* out = (float*)d_out;

    cudaFuncSetAttribute(combo_kernel, cudaFuncAttributeMaxDynamicSharedMemorySize, S1_SMEM);
    cudaFuncSetAttribute(edge_kernel,  cudaFuncAttributeMaxDynamicSharedMemorySize, TSZ * 2);

    // 1: histS + histD + P-transpose
    prep_kernel<<<2 * HIST_BLOCKS + TP_BLOCKS, 256>>>(src, dst,
                                                      P000, P110, P220, P011, P101,
                                                      P121, P211, P111, P022, P112,
                                                      P202, P222, P212);
    // 2: both scans
    scan2_kernel<<<2, 1024>>>();
    // 3: scatterS + scatterD + stage1
    combo_kernel<<<2 * HIST_BLOCKS + S1_BLOCKS, 256, S1_SMEM>>>(src, dst, x_a, x_v, x_d);
    // 4: edge  <-- ncu capture slot
    edge_kernel<<<NODES, 256, TSZ * 2>>>(rij);
    // 5: gather
    gather_kernel<<<NODES / 8, 256>>>(out);
}

// round 17
// speedup vs baseline: 2.3025x; 1.0257x over previous
#include <cuda_runtime.h>
#include <cuda_fp16.h>
#include <math.h>

#define NODES 16384
#define EDGES 262144
#define TSZ   13184
#define OUTC  304

// per-node t layout offsets (half elements), all [l][ang][c], c fastest
// family 220 is symmetrized: ANG=6 (a6: 00,11,22,01,02,12)
#define O000  0
#define O110  512
#define O220  2048
#define O011  5120
#define O101  5888
#define O121  6144
#define O211  8448
#define O111  9216
#define O022  9984
#define O112  11136
#define O202  11520
#define O222  11648
#define O212  12800

// transposed-P offsets in g_Pt (floats), layout [l][b][c] per family
#define T000  0
#define T110  32768
#define T220  49152
#define T011  57344
#define T101  65536
#define T121  81920
#define T211  86016
#define T111  94208
#define T022  102400
#define T112  104448
#define T202  108544
#define T222  116736
#define T212  118784
#define TPTOT 122880

#define NT 16                        // nodes per stage1 block
#define SX_SZ   (400 * NT)           // floats: 304 base features + 96 symmetrized xd
#define STG_STR 260                  // floats per node row in staging
#define STG_HALF (NT * STG_STR)
#define S1_SMEM ((SX_SZ + 2 * STG_HALF) * 4)

#define HIST_BLOCKS  (EDGES / 256)   // 1024
#define TP_BLOCKS    (TPTOT / 256 + 1)
#define S1_BLOCKS    (NODES / NT)    // 1024

typedef unsigned long long ull;

__device__ __half g_t[(size_t)NODES * TSZ];           // 432 MB scratch (fp16)
__device__ __half g_m[(size_t)EDGES * OUTC];          // 159 MB per-edge messages (fp16)
__device__ float  g_Pt[TPTOT];                        // transposed P, c-fastest
__device__ int g_cntS[NODES], g_curS[NODES], g_startS[NODES + 1], g_sortS[EDGES];
__device__ int g_cntD[NODES], g_curD[NODES], g_startD[NODES + 1], g_sortD[EDGES];

// ---- packed f32x2 helpers ----
__device__ __forceinline__ ull dup2(float x) {
    ull r; asm("mov.b64 %0, {%1, %1};" : "=l"(r) : "f"(x)); return r;
}
__device__ __forceinline__ void fma2(ull& a, ull b, ull c) {
    asm("fma.rn.f32x2 %0, %1, %2, %0;" : "+l"(a) : "l"(b), "l"(c));
}
__device__ __forceinline__ float2 unpk2(ull a) {
    float2 f; asm("mov.b64 {%0, %1}, %2;" : "=f"(f.x), "=f"(f.y) : "l"(a)); return f;
}

// ---------------- P transpose helper: P[c][l][b] -> Pt[l][b][c] ----------------
__device__ __forceinline__ void tp1(const float* __restrict__ P, float* __restrict__ Pt,
                                    int i, int C, int B) {
    const int b = i % B;
    const int l = (i / B) % 8;
    const int c = i / (8 * B);
    Pt[(l * B + b) * C + c] = P[i];
}

// ---------------- launch 1: histS + histD + transpose fused ----------------
__global__ void prep_kernel(
    const int* __restrict__ src, const int* __restrict__ dst,
    const float* __restrict__ P000, const float* __restrict__ P110, const float* __restrict__ P220,
    const float* __restrict__ P011, const float* __restrict__ P101, const float* __restrict__ P121,
    const float* __restrict__ P211, const float* __restrict__ P111, const float* __restrict__ P022,
    const float* __restrict__ P112, const float* __restrict__ P202, const float* __restrict__ P222,
    const float* __restrict__ P212)
{
    if (blockIdx.x < HIST_BLOCKS) {
        int i = blockIdx.x * 256 + threadIdx.x;
        atomicAdd(&g_cntS[src[i]], 1);
    } else if (blockIdx.x < 2 * HIST_BLOCKS) {
        int i = (blockIdx.x - HIST_BLOCKS) * 256 + threadIdx.x;
        atomicAdd(&g_cntD[dst[i]], 1);
    } else {
        int i = (blockIdx.x - 2 * HIST_BLOCKS) * 256 + threadIdx.x;
        if      (i < T110)  tp1(P000, g_Pt + T000, i - T000, 64, 64);
        else if (i < T220)  tp1(P110, g_Pt + T110, i - T110, 64, 32);
        else if (i < T011)  tp1(P220, g_Pt + T220, i - T220, 64, 16);
        else if (i < T101)  tp1(P011, g_Pt + T011, i - T011, 32, 32);
        else if (i < T121)  tp1(P101, g_Pt + T101, i - T101, 32, 64);
        else if (i < T211)  tp1(P121, g_Pt + T121, i - T121, 32, 16);
        else if (i < T111)  tp1(P211, g_Pt + T211, i - T211, 32, 32);
        else if (i < T022)  tp1(P111, g_Pt + T111, i - T111, 32, 32);
        else if (i < T112)  tp1(P022, g_Pt + T022, i - T022, 16, 16);
        else if (i < T202)  tp1(P112, g_Pt + T112, i - T112, 16, 32);
        else if (i < T222)  tp1(P202, g_Pt + T202, i - T202, 16, 64);
        else if (i < T212)  tp1(P222, g_Pt + T222, i - T222, 16, 16);
        else if (i < TPTOT) tp1(P212, g_Pt + T212, i - T212, 16, 32);
    }
}

// ---------------- launch 2: both scans, one kernel ----------------
__device__ __forceinline__ void scan_body(const int* __restrict__ cnt, int* __restrict__ start) {
    __shared__ int ssum[1024];
    int t = threadIdx.x;
    int loc[16];
    int s = 0;
    int base = t * 16;
    #pragma unroll
    for (int i = 0; i < 16; i++) { loc[i] = s; s += cnt[base + i]; }
    ssum[t] = s;
    __syncthreads();
    for (int off = 1; off < 1024; off <<= 1) {
        int v = (t >= off) ? ssum[t - off] : 0;
        __syncthreads();
        if (t >= off) ssum[t] += v;
        __syncthreads();
    }
    int excl = (t == 0) ? 0 : ssum[t - 1];
    #pragma unroll
    for (int i = 0; i < 16; i++) start[base + i] = excl + loc[i];
    if (t == 0) start[NODES] = EDGES;
}

__global__ void scan2_kernel() {
    if (blockIdx.x == 0) scan_body(g_cntS, g_startS);
    else                 scan_body(g_cntD, g_startD);
}

// ---------------- stage 1: f32x2, l-paired, staged flush (220 symmetrized) ----------------

__device__ __forceinline__ void flush_chunk16(const float* __restrict__ stg,
                                              __half* __restrict__ tg,
                                              int off, int cols) {
    const int warp = threadIdx.x >> 5, lane = threadIdx.x & 31;
    if (lane * 8 < cols) {
        #pragma unroll
        for (int n2 = 0; n2 < 2; n2++) {
            const int n = warp * 2 + n2;
            const float* s = stg + n * STG_STR + lane * 8;
            float4 f0 = *reinterpret_cast<const float4*>(s);
            float4 f1 = *reinterpret_cast<const float4*>(s + 4);
            __half2 h0 = __floats2half2_rn(f0.x, f0.y);
            __half2 h1 = __floats2half2_rn(f0.z, f0.w);
            __half2 h2 = __floats2half2_rn(f1.x, f1.y);
            __half2 h3 = __floats2half2_rn(f1.z, f1.w);
            uint4 v;
            v.x = *reinterpret_cast<unsigned*>(&h0);
            v.y = *reinterpret_cast<unsigned*>(&h1);
            v.z = *reinterpret_cast<unsigned*>(&h2);
            v.w = *reinterpret_cast<unsigned*>(&h3);
            *reinterpret_cast<uint4*>(tg + (size_t)n * TSZ + off + lane * 8) = v;
        }
    }
}

template<int C, int B, int ANG, int ANGX>
__device__ __forceinline__ void fam3(const float* __restrict__ Pt,
                                     const float* __restrict__ sx,
                                     int xoff, float* __restrict__ stgA,
                                     float* __restrict__ stgB,
                                     __half* __restrict__ tg, int toff) {
    const int tid = threadIdx.x;
    const int NEH = 4 * ANG * C;
    for (int cb = 0; cb < NEH; cb += 256) {
        const int e = cb + tid;
        if (e < NEH) {
            const int c  = e % C;
            const int la = e / C;
            const int a  = la % ANG;
            const int l  = la / ANG;
            const ull* xb = reinterpret_cast<const ull*>(sx) + (xoff + a) * (NT / 2);
            ull acc0[8], acc1[8];
            #pragma unroll
            for (int np = 0; np < 8; np++) { acc0[np] = 0ull; acc1[np] = 0ull; }
            const float* PlA = Pt + (l * B) * C + c;
            const float* PlB = Pt + ((l + 4) * B) * C + c;
            #pragma unroll 1
            for (int bc = 0; bc < B; bc += 8) {
                ull pA[8], pB[8];
                #pragma unroll
                for (int j = 0; j < 8; j++) {
                    pA[j] = dup2(PlA[(bc + j) * C]);
                    pB[j] = dup2(PlB[(bc + j) * C]);
                }
                #pragma unroll
                for (int j = 0; j < 8; j++) {
                    #pragma unroll
                    for (int np = 0; np < 8; np++) {
                        ull xv = xb[(bc + j) * ANGX * 8 + np];
                        fma2(acc0[np], pA[j], xv);
                        fma2(acc1[np], pB[j], xv);
                    }
                }
            }
            #pragma unroll
            for (int np = 0; np < 8; np++) {
                float2 r0 = unpk2(acc0[np]);
                float2 r1 = unpk2(acc1[np]);
                stgA[(2 * np)     * STG_STR + tid] = r0.x;
                stgA[(2 * np + 1) * STG_STR + tid] = r0.y;
                stgB[(2 * np)     * STG_STR + tid] = r1.x;
                stgB[(2 * np + 1) * STG_STR + tid] = r1.y;
            }
        }
        __syncthreads();
        const int cols = min(256, NEH - cb);
        flush_chunk16(stgA, tg, toff + cb, cols);
        flush_chunk16(stgB, tg, toff + NEH + cb, cols);
        __syncthreads();
    }
}

__device__ __forceinline__ void stage1_body(
    const float* __restrict__ xa, const float* __restrict__ xv, const float* __restrict__ xd,
    int blk)
{
    extern __shared__ float smem[];
    float* sx   = smem;
    float* stgA = smem + SX_SZ;
    float* stgB = smem + SX_SZ + STG_HALF;
    const int node0 = blk * NT;
    const int tid = threadIdx.x;
    for (int i = tid; i < NT * 64;  i += 256) { int n = i / 64,  f = i % 64;        sx[f * 16 + n] = xa[node0 * 64  + i]; }
    for (int i = tid; i < NT * 96;  i += 256) { int n = i / 96,  f = 64 + i % 96;   sx[f * 16 + n] = xv[node0 * 96  + i]; }
    for (int i = tid; i < NT * 144; i += 256) { int n = i / 144, f = 160 + i % 144; sx[f * 16 + n] = xd[node0 * 144 + i]; }
    // symmetrized xd: f = 304 + b*6 + a6, a6: {00,11,22,01,02,12}; offdiag = xd[ij]+xd[ji]
    for (int i = tid; i < NT * 96; i += 256) {
        const int n = i / 96, f6 = i % 96, b = f6 / 6, a6 = f6 % 6;
        const int ii6[6] = {0, 1, 2, 0, 0, 1};
        const int jj6[6] = {0, 1, 2, 1, 2, 2};
        const float* xdn = xd + (size_t)(node0 + n) * 144 + b * 9;
        float v = xdn[ii6[a6] * 3 + jj6[a6]];
        if (a6 >= 3) v += xdn[jj6[a6] * 3 + ii6[a6]];
        sx[(304 + f6) * 16 + n] = v;
    }
    __syncthreads();
    __half* tg = g_t + (size_t)node0 * TSZ;
    fam3<64, 64, 1, 1>(g_Pt + T000, sx, 0,   stgA, stgB, tg, O000);
    fam3<32, 64, 1, 1>(g_Pt + T101, sx, 0,   stgA, stgB, tg, O101);
    fam3<16, 64, 1, 1>(g_Pt + T202, sx, 0,   stgA, stgB, tg, O202);
    fam3<64, 32, 3, 3>(g_Pt + T110, sx, 64,  stgA, stgB, tg, O110);
    fam3<64, 16, 6, 6>(g_Pt + T220, sx, 304, stgA, stgB, tg, O220);   // symmetrized
    fam3<32, 32, 3, 3>(g_Pt + T011, sx, 64,  stgA, stgB, tg, O011);
    fam3<32, 16, 9, 9>(g_Pt + T121, sx, 160, stgA, stgB, tg, O121);
    fam3<32, 32, 3, 3>(g_Pt + T211, sx, 64,  stgA, stgB, tg, O211);
    fam3<32, 32, 3, 3>(g_Pt + T111, sx, 64,  stgA, stgB, tg, O111);
    fam3<16, 16, 9, 9>(g_Pt + T022, sx, 160, stgA, stgB, tg, O022);
    fam3<16, 32, 3, 3>(g_Pt + T112, sx, 64,  stgA, stgB, tg, O112);
    fam3<16, 16, 9, 9>(g_Pt + T222, sx, 160, stgA, stgB, tg, O222);
    fam3<16, 32, 3, 3>(g_Pt + T212, sx, 64,  stgA, stgB, tg, O212);
}

// ---------------- launch 3: scatterS + scatterD + stage1 fused ----------------
__global__ void __launch_bounds__(256, 2) combo_kernel(
    const int* __restrict__ src, const int* __restrict__ dst,
    const float* __restrict__ xa, const float* __restrict__ xv, const float* __restrict__ xd)
{
    if (blockIdx.x < HIST_BLOCKS) {
        int i = blockIdx.x * 256 + threadIdx.x;
        int sn = src[i];
        int p = g_startS[sn] + atomicAdd(&g_curS[sn], 1);
        g_sortS[p] = i;
    } else if (blockIdx.x < 2 * HIST_BLOCKS) {
        int i = (blockIdx.x - HIST_BLOCKS) * 256 + threadIdx.x;
        int dn = dst[i];
        int p = g_startD[dn] + atomicAdd(&g_curD[dn], 1);
        g_sortD[p] = i;
    } else {
        stage1_body(xa, xv, xd, blockIdx.x - 2 * HIST_BLOCKS);
    }
}

// ---------------- stage 2a: per-edge contraction, fp16 smem tile, fp16 messages ----------------

__device__ __forceinline__ void edge_geom(const float* __restrict__ rij, int e,
                                          float* rad, float* rh, float* rr) {
    const float rx = rij[3 * e + 0], ry = rij[3 * e + 1], rz = rij[3 * e + 2];
    const float xsq = (rx * rx + ry * ry + rz * rz) * 0.125f;
    const float env = fmaxf(0.f, 1.f - xsq);
    const float c1  = cosf(3.14159265358979f * sqrtf(xsq));
    rad[0] = env; rad[1] = c1 * env;
    float cm2 = 1.f, cm1 = c1;
    #pragma unroll
    for (int l = 2; l < 8; l++) {
        float cn = 2.f * c1 * cm1 - cm2;
        rad[l] = cn * env;
        cm2 = cm1; cm1 = cn;
    }
    const float vx = rx * 0.875f, vy = ry * 0.875f, vz = rz * 0.875f;
    const float nr = sqrtf(vx * vx + vy * vy + vz * vz);
    const float sc = tanhf(nr) / fmaxf(nr, 1e-6f);
    rh[0] = vx * sc; rh[1] = vy * sc; rh[2] = vz * sc;
    #pragma unroll
    for (int i = 0; i < 3; i++)
        #pragma unroll
        for (int j = 0; j < 3; j++) rr[i * 3 + j] = rh[i] * rh[j];
}

__device__ __forceinline__ float ldh(const __half* __restrict__ st, int idx) {
    return __half2float(st[idx]);
}

__global__ void __launch_bounds__(256, 4) edge_kernel(
    const float* __restrict__ rij)
{
    extern __shared__ __half st[];
    const int n   = blockIdx.x;
    const int tid = threadIdx.x;
    // raw fp16 tile copy (no conversion)
    {
        const uint4* tg = reinterpret_cast<const uint4*>(g_t + (size_t)n * TSZ);
        uint4* st4 = reinterpret_cast<uint4*>(st);
        for (int i = tid; i < TSZ / 8; i += 256) st4[i] = tg[i];
    }
    __syncthreads();
    const int s0 = g_startS[n], s1 = g_startS[n + 1];
    const int warp = tid >> 5, lane = tid & 31;
    const int c16 = lane & 15;

    for (int k = s0 + 2 * warp; k < s1; k += 16) {
        const int eA = g_sortS[k];
        const bool vB = (k + 1 < s1);
        const int eB = g_sortS[vB ? k + 1 : k];
        __half* mA = g_m + (size_t)eA * OUTC;
        __half* mB = g_m + (size_t)eB * OUTC;
        float radA[8], rhA[3], rrA[9], radB[8], rhB[3], rrB[9];
        edge_geom(rij, eA, radA, rhA, rrA);
        edge_geom(rij, eB, radB, rhB, rrB);

        // ---------- m_a : channels 2*lane, 2*lane+1 via half2 loads (220 symmetrized) ----------
        {
            float a0A = 0.f, a1A = 0.f, a0B = 0.f, a1B = 0.f;
            #pragma unroll
            for (int l = 0; l < 8; l++) {
                const float2 p0 = __half22float2(*reinterpret_cast<const __half2*>(st + O000 + l * 64 + 2 * lane));
                float sxA = p0.x, syA = p0.y, sxB = p0.x, syB = p0.y;
                #pragma unroll
                for (int i = 0; i < 3; i++) {
                    const float2 p = __half22float2(*reinterpret_cast<const __half2*>(st + O110 + (l * 3 + i) * 64 + 2 * lane));
                    sxA += rhA[i] * p.x; syA += rhA[i] * p.y;
                    sxB += rhB[i] * p.x; syB += rhB[i] * p.y;
                }
                #pragma unroll
                for (int a = 0; a < 6; a++) {
                    const int map6[6] = {0, 4, 8, 1, 2, 5};   // rr index per a6
                    const int m = map6[a];
                    const float2 p = __half22float2(*reinterpret_cast<const __half2*>(st + O220 + (l * 6 + a) * 64 + 2 * lane));
                    sxA += rrA[m] * p.x; syA += rrA[m] * p.y;
                    sxB += rrB[m] * p.x; syB += rrB[m] * p.y;
                }
                a0A += radA[l] * sxA; a1A += radA[l] * syA;
                a0B += radB[l] * sxB; a1B += radB[l] * syB;
            }
            *reinterpret_cast<__half2*>(mA + 2 * lane) = __floats2half2_rn(a0A, a1A);
            if (vB) *reinterpret_cast<__half2*>(mB + 2 * lane) = __floats2half2_rn(a0B, a1B);
        }

        // ---------- m_v : channel c = lane ----------
        {
            float vA[3] = {0, 0, 0}, uA[3] = {0, 0, 0}, SA = 0.f;
            float vB3[3] = {0, 0, 0}, uB[3] = {0, 0, 0}, SB = 0.f;
            #pragma unroll
            for (int l = 0; l < 8; l++) {
                float t011[3], t211[3], t111[3], t121[9];
                const float t101 = ldh(st, O101 + l * 32 + lane);
                #pragma unroll
                for (int i = 0; i < 3; i++) {
                    t011[i] = ldh(st, O011 + (l * 3 + i) * 32 + lane);
                    t211[i] = ldh(st, O211 + (l * 3 + i) * 32 + lane);
                    t111[i] = ldh(st, O111 + (l * 3 + i) * 32 + lane);
                }
                #pragma unroll
                for (int a = 0; a < 9; a++) t121[a] = ldh(st, O121 + (l * 9 + a) * 32 + lane);

                float sSA = t101, sSB = t101;
                #pragma unroll
                for (int j = 0; j < 3; j++) { sSA += rhA[j] * t211[j]; sSB += rhB[j] * t211[j]; }
                SA += radA[l] * sSA; SB += radB[l] * sSB;
                #pragma unroll
                for (int i = 0; i < 3; i++) {
                    float svA = t011[i], svB = t011[i];
                    #pragma unroll
                    for (int j = 0; j < 3; j++) {
                        svA += rhA[j] * t121[i * 3 + j];
                        svB += rhB[j] * t121[i * 3 + j];
                    }
                    vA[i]  += radA[l] * svA;
                    vB3[i] += radB[l] * svB;
                    uA[i]  += radA[l] * t111[i];
                    uB[i]  += radB[l] * t111[i];
                }
            }
            vA[0]  += SA * rhA[0] + (rhA[1] * uA[2] - rhA[2] * uA[1]);
            vA[1]  += SA * rhA[1] + (rhA[2] * uA[0] - rhA[0] * uA[2]);
            vA[2]  += SA * rhA[2] + (rhA[0] * uA[1] - rhA[1] * uA[0]);
            vB3[0] += SB * rhB[0] + (rhB[1] * uB[2] - rhB[2] * uB[1]);
            vB3[1] += SB * rhB[1] + (rhB[2] * uB[0] - rhB[0] * uB[2]);
            vB3[2] += SB * rhB[2] + (rhB[0] * uB[1] - rhB[1] * uB[0]);
            #pragma unroll
            for (int i = 0; i < 3; i++) mA[64 + lane * 3 + i] = __float2half_rn(vA[i]);
            if (vB) {
                #pragma unroll
                for (int i = 0; i < 3; i++) mB[64 + lane * 3 + i] = __float2half_rn(vB3[i]);
            }
        }

        // ---------- m_d : c = lane&15, half-warps split the l-sum ----------
        {
            const int hh = lane >> 4;
            float radhA[4], radhB[4];
            #pragma unroll
            for (int i = 0; i < 4; i++) {
                radhA[i] = (hh == 0) ? radA[i] : radA[4 + i];
                radhB[i] = (hh == 0) ? radB[i] : radB[4 + i];
            }
            float outA[9] = {0,0,0,0,0,0,0,0,0};
            float outB[9] = {0,0,0,0,0,0,0,0,0};
            #pragma unroll
            for (int ll = 0; ll < 4; ll++) {
                const int l = hh * 4 + ll;
                float t022[9], t222[9], t112[3], t212[3];
                const float t202 = ldh(st, O202 + l * 16 + c16);
                #pragma unroll
                for (int a = 0; a < 9; a++) {
                    t022[a] = ldh(st, O022 + (l * 9 + a) * 16 + c16);
                    t222[a] = ldh(st, O222 + (l * 9 + a) * 16 + c16);
                }
                #pragma unroll
                for (int j = 0; j < 3; j++) {
                    t112[j] = ldh(st, O112 + (l * 3 + j) * 16 + c16);
                    t212[j] = ldh(st, O212 + (l * 3 + j) * 16 + c16);
                }
                float qA[3], qB[3];
                #pragma unroll
                for (int j = 0; j < 3; j++) {
                    qA[j] = t112[j] + rhA[0] * t222[j] + rhA[1] * t222[3 + j] + rhA[2] * t222[6 + j];
                    qB[j] = t112[j] + rhB[0] * t222[j] + rhB[1] * t222[3 + j] + rhB[2] * t222[6 + j];
                }
                qA[0] += rhA[1] * t212[2] - rhA[2] * t212[1];
                qA[1] += rhA[2] * t212[0] - rhA[0] * t212[2];
                qA[2] += rhA[0] * t212[1] - rhA[1] * t212[0];
                qB[0] += rhB[1] * t212[2] - rhB[2] * t212[1];
                qB[1] += rhB[2] * t212[0] - rhB[0] * t212[2];
                qB[2] += rhB[0] * t212[1] - rhB[1] * t212[0];
                #pragma unroll
                for (int ij = 0; ij < 9; ij++) {
                    const int i = ij / 3, j = ij % 3;
                    outA[ij] += radhA[ll] * (t022[ij] + rrA[ij] * t202 + rhA[i] * qA[j]);
                    outB[ij] += radhB[ll] * (t022[ij] + rrB[ij] * t202 + rhB[i] * qB[j]);
                }
            }
            #pragma unroll
            for (int ij = 0; ij < 9; ij++) {
                outA[ij] += __shfl_xor_sync(0xffffffffu, outA[ij], 16);
                outB[ij] += __shfl_xor_sync(0xffffffffu, outB[ij], 16);
            }
            #pragma unroll
            for (int ij = 0; ij < 9; ij++) {
                const bool mine = (hh == 0) ? (ij < 5) : (ij >= 5);
                if (mine) {
                    mA[160 + c16 * 9 + ij] = __float2half_rn(outA[ij]);
                    if (vB) mB[160 + c16 * 9 + ij] = __float2half_rn(outB[ij]);
                }
            }
        }
    }
}

// ---------------- launch 5: dst-grouped segment sum (fp16 in, fp32 accumulate/out) ----------------
__global__ void __launch_bounds__(256) gather_kernel(float* __restrict__ out) {
    const int warp = threadIdx.x >> 5, lane = threadIdx.x & 31;
    const int node = blockIdx.x * 8 + warp;
    // 304 halves = 38 uint4 chunks of 8 halves; lane handles chunk lane, plus lane+32 if lane<6
    float acc0[8] = {0, 0, 0, 0, 0, 0, 0, 0};
    float acc1[8] = {0, 0, 0, 0, 0, 0, 0, 0};
    const bool extra = (lane < 6);
    const int c0 = lane, c1 = lane + 32;
    const int s0 = g_startD[node], s1 = g_startD[node + 1];
    for (int k = s0; k < s1; k++) {
        const int e = g_sortD[k];
        const uint4* row = reinterpret_cast<const uint4*>(g_m + (size_t)e * OUTC);
        uint4 r = row[c0];
        const __half2* h = reinterpret_cast<const __half2*>(&r);
        #pragma unroll
        for (int j = 0; j < 4; j++) {
            float2 f = __half22float2(h[j]);
            acc0[2 * j] += f.x; acc0[2 * j + 1] += f.y;
        }
        if (extra) {
            uint4 r2 = row[c1];
            const __half2* h2 = reinterpret_cast<const __half2*>(&r2);
            #pragma unroll
            for (int j = 0; j < 4; j++) {
                float2 f = __half22float2(h2[j]);
                acc1[2 * j] += f.x; acc1[2 * j + 1] += f.y;
            }
        }
    }
    float* orow = out + (size_t)node * OUTC;
    *reinterpret_cast<float4*>(orow + c0 * 8)     = make_float4(acc0[0], acc0[1], acc0[2], acc0[3]);
    *reinterpret_cast<float4*>(orow + c0 * 8 + 4) = make_float4(acc0[4], acc0[5], acc0[6], acc0[7]);
    if (extra) {
        *reinterpret_cast<float4*>(orow + c1 * 8)     = make_float4(acc1[0], acc1[1], acc1[2], acc1[3]);
        *reinterpret_cast<float4*>(orow + c1 * 8 + 4) = make_float4(acc1[4], acc1[5], acc1[6], acc1[7]);
    }

    const int gt = blockIdx.x * 256 + threadIdx.x;
    if (gt < NODES) { g_cntS[gt] = 0; g_curS[gt] = 0; g_cntD[gt] = 0; g_curD[gt] = 0; }
}

extern "C" void kernel_launch(void* const* d_in, const int* in_sizes, int n_in,
                              void* d_out, int out_size) {
    const float* x_a  = (const float*)d_in[0];
    const float* x_v  = (const float*)d_in[1];
    const float* x_d  = (const float*)d_in[2];
    const float* rij  = (const float*)d_in[3];
    const float* P000 = (const float*)d_in[4];
    const float* P110 = (const float*)d_in[5];
    const float* P220 = (const float*)d_in[6];
    const float* P011 = (const float*)d_in[7];
    const float* P101 = (const float*)d_in[8];
    const float* P121 = (const float*)d_in[9];
    const float* P211 = (const float*)d_in[10];
    const float* P111 = (const float*)d_in[11];
    const float* P022 = (const float*)d_in[12];
    const float* P112 = (const float*)d_in[13];
    const float* P202 = (const float*)d_in[14];
    const float* P222 = (const float*)d_in[15];
    const float* P212 = (const float*)d_in[16];
    const int*   src  = (const int*)d_in[17];
    const int*   dst  = (const int*)d_in[18];
    float* out = (float*)d_out;

    cudaFuncSetAttribute(combo_kernel, cudaFuncAttributeMaxDynamicSharedMemorySize, S1_SMEM);
    cudaFuncSetAttribute(edge_kernel,  cudaFuncAttributeMaxDynamicSharedMemorySize, TSZ * 2);

    // 1: histS + histD + P-transpose
    prep_kernel<<<2 * HIST_BLOCKS + TP_BLOCKS, 256>>>(src, dst,
                                                      P000, P110, P220, P011, P101,
                                                      P121, P211, P111, P022, P112,
                                                      P202, P222, P212);
    // 2: both scans
    scan2_kernel<<<2, 1024>>>();
    // 3: scatterS + scatterD + stage1
    combo_kernel<<<2 * HIST_BLOCKS + S1_BLOCKS, 256, S1_SMEM>>>(src, dst, x_a, x_v, x_d);
    // 4: edge  <-- ncu capture slot
    edge_kernel<<<NODES, 256, TSZ * 2>>>(rij);
    // 5: gather
    gather_kernel<<<NODES / 8, 256>>>(out);
}